// round 10
// baseline (speedup 1.0000x reference)
#include <cuda_runtime.h>
#include <cuda_bf16.h>
#include <cstdint>
#include <cstddef>

#define BATCH 32
#define TT    1024
#define II    512
#define HH    512
#define G3    1536
#define NCTA_PER_DIR 32

// ---------------- device scratch ----------------
__device__ float d_xn[(size_t)BATCH * TT * II];
__device__ float d_xp[(size_t)2 * TT * G3 * BATCH];
__device__ float d_wihr[2 * G3 * II];
__device__ float d_whpf[2 * NCTA_PER_DIR * 64 * 384];
__device__ float d_h[2 * 4 * 16384];                    // h 4-deep ring [dir][buf][16384]
__device__ unsigned int d_f1[2 * 32 * 32];              // produce flags, 128B padded
__device__ unsigned int d_gsync[2 * 256];               // gemm t-block completion counters

// ---------------- helpers ----------------
__device__ __forceinline__ float tf32r(float x) {
    uint32_t u; asm("cvt.rna.tf32.f32 %0, %1;" : "=r"(u) : "f"(x));
    return __uint_as_float(u);
}
__device__ __forceinline__ void cp16(void* smem_dst, const void* gmem_src) {
    uint32_t s = (uint32_t)__cvta_generic_to_shared(smem_dst);
    asm volatile("cp.async.cg.shared.global [%0], [%1], 16;" :: "r"(s), "l"(gmem_src));
}
__device__ __forceinline__ void cp_commit() { asm volatile("cp.async.commit_group;"); }
template <int N> __device__ __forceinline__ void cp_wait() {
    asm volatile("cp.async.wait_group %0;" :: "n"(N));
}
__device__ __forceinline__ unsigned ldacq(const unsigned* p) {
    unsigned v; asm volatile("ld.acquire.gpu.global.u32 %0, [%1];" : "=r"(v) : "l"(p)); return v;
}
__device__ __forceinline__ void strlx(unsigned* p, unsigned v) {
    asm volatile("st.relaxed.gpu.global.u32 [%0], %1;" :: "l"(p), "r"(v));
}
__device__ __forceinline__ void mma_tf32(float* d, const uint32_t* a, const uint32_t* b) {
    asm volatile(
        "mma.sync.aligned.m16n8k8.row.col.f32.tf32.tf32.f32 "
        "{%0,%1,%2,%3},{%4,%5,%6,%7},{%8,%9},{%0,%1,%2,%3};"
        : "+f"(d[0]), "+f"(d[1]), "+f"(d[2]), "+f"(d[3])
        : "r"(a[0]), "r"(a[1]), "r"(a[2]), "r"(a[3]), "r"(b[0]), "r"(b[1]));
}
__device__ __forceinline__ void mma_tf32_f(float* d, const float4& a, const float2& b) {
    asm volatile(
        "mma.sync.aligned.m16n8k8.row.col.f32.tf32.tf32.f32 "
        "{%0,%1,%2,%3},{%4,%5,%6,%7},{%8,%9},{%0,%1,%2,%3};"
        : "+f"(d[0]), "+f"(d[1]), "+f"(d[2]), "+f"(d[3])
        : "r"(__float_as_uint(a.x)), "r"(__float_as_uint(a.y)),
          "r"(__float_as_uint(a.z)), "r"(__float_as_uint(a.w)),
          "r"(__float_as_uint(b.x)), "r"(__float_as_uint(b.y)));
}
__device__ __forceinline__ int gate_row(int c, int j) {
    return (j < 16) ? (c * 16 + j)
         : (j < 32) ? (512 + c * 16 + (j - 16))
                    : (1024 + c * 16 + (j - 32));
}

// ---------------- kernel 0: prep ----------------
__global__ void prep_kernel(const float* __restrict__ wihf, const float* __restrict__ whhf,
                            const float* __restrict__ wihb, const float* __restrict__ whhb) {
    int idx = blockIdx.x * blockDim.x + threadIdx.x;
    int stride = gridDim.x * blockDim.x;
    for (int i = idx; i < 2 * G3 * II; i += stride) {
        int dir = i / (G3 * II);
        int r = i - dir * (G3 * II);
        d_wihr[i] = tf32r((dir ? wihb : wihf)[r]);
    }
    for (int i = idx; i < 2 * NCTA_PER_DIR * 64 * 384; i += stride) {
        int reg  = i & 3;
        int lane = (i >> 2) & 31;
        int mi   = (i % 384) / 128;
        int kk   = (i / 384) & 63;
        int c    = (i / (384 * 64)) % NCTA_PER_DIR;
        int dir  = i / (384 * 64 * NCTA_PER_DIR);
        int j = mi * 16 + (lane >> 2) + 8 * (reg & 1);
        int k = kk * 8 + (lane & 3) + 4 * (reg >> 1);
        const float* w = dir ? whhb : whhf;
        d_whpf[i] = tf32r(w[gate_row(c, j) * II + k]);
    }
    for (int i = idx; i < 2 * 4 * 16384; i += stride) d_h[i] = 0.0f;
    for (int i = idx; i < 2 * 32 * 32; i += stride) d_f1[i] = 0u;
    for (int i = idx; i < 2 * 256; i += stride) d_gsync[i] = 0u;
}

// ---------------- kernel 1: LayerNorm ----------------
__global__ void ln_kernel(const float* __restrict__ x, const float* __restrict__ gamma,
                          const float* __restrict__ beta) {
    int row = blockIdx.x;
    const float* xr = x + (size_t)row * II;
    int tid = threadIdx.x;
    float v[4]; float s = 0.f, q = 0.f;
#pragma unroll
    for (int k = 0; k < 4; k++) {
        v[k] = xr[tid + 128 * k];
        s += v[k]; q += v[k] * v[k];
    }
#pragma unroll
    for (int o = 16; o > 0; o >>= 1) {
        s += __shfl_xor_sync(0xffffffffu, s, o);
        q += __shfl_xor_sync(0xffffffffu, q, o);
    }
    __shared__ float ws[4], wq[4];
    if ((tid & 31) == 0) { ws[tid >> 5] = s; wq[tid >> 5] = q; }
    __syncthreads();
    s = ws[0] + ws[1] + ws[2] + ws[3];
    q = wq[0] + wq[1] + wq[2] + wq[3];
    float mu = s * (1.0f / 512.0f);
    float var = q * (1.0f / 512.0f) - mu * mu;
    float rstd = rsqrtf(var + 1e-5f);
#pragma unroll
    for (int k = 0; k < 4; k++) {
        int i = tid + 128 * k;
        d_xn[(size_t)row * II + i] = tf32r((v[k] - mu) * rstd * gamma[i] + beta[i]);
    }
}

// ---------------- kernel 2: input-projection GEMM (both-ends time order + progress flags) ----------------
#define GEMM_BUF_FLOATS (128 * 36)
__global__ void __launch_bounds__(256)
gemm_kernel(const float* __restrict__ bihf, const float* __restrict__ bihb) {
    extern __shared__ float smem[];
    float* As = smem;
    float* Bs = smem + 2 * GEMM_BUF_FLOATS;
    // grid (12, 512): x = by (row tile), y -> (dir, time-block from both ends inward)
    int by  = blockIdx.x;
    int yb2 = blockIdx.y;
    int dir = yb2 & 1;
    int yb  = yb2 >> 1;                                  // 0..255
    int bx  = (yb & 1) ? (255 - (yb >> 1)) : (yb >> 1);  // 0,255,1,254,...
    int tid = threadIdx.x, lane = tid & 31, wid = tid >> 5;
    int wm = wid & 1, wn = wid >> 1;
    const float* bih = dir ? bihb : bihf;
    const float* Abase = d_wihr + (size_t)dir * G3 * II + (size_t)(by * 128) * II;

    auto load_tiles = [&](int kb, int buf) {
        float* As_ = As + buf * GEMM_BUF_FLOATS;
        float* Bs_ = Bs + buf * GEMM_BUF_FLOATS;
#pragma unroll
        for (int u = 0; u < 4; u++) {
            int o = tid + 256 * u;
            int row = o >> 3, seg = o & 7;
            cp16(&As_[row * 36 + seg * 4], Abase + (size_t)row * II + kb * 32 + seg * 4);
        }
#pragma unroll
        for (int u = 0; u < 4; u++) {
            int o = tid + 256 * u;
            int col = o >> 3, seg = o & 7;
            int n = bx * 128 + col;
            int t = n >> 5, b = n & 31;
            cp16(&Bs_[col * 36 + seg * 4], d_xn + ((size_t)b * TT + t) * II + kb * 32 + seg * 4);
        }
    };

    float acc[4][4][4];
#pragma unroll
    for (int i = 0; i < 4; i++)
#pragma unroll
        for (int j = 0; j < 4; j++)
#pragma unroll
            for (int k = 0; k < 4; k++) acc[i][j][k] = 0.f;

    load_tiles(0, 0); cp_commit();
    for (int kb = 0; kb < 16; kb++) {
        if (kb + 1 < 16) { load_tiles(kb + 1, (kb + 1) & 1); cp_commit(); cp_wait<1>(); }
        else cp_wait<0>();
        __syncthreads();
        float* As_ = As + (kb & 1) * GEMM_BUF_FLOATS;
        float* Bs_ = Bs + (kb & 1) * GEMM_BUF_FLOATS;
#pragma unroll
        for (int ks = 0; ks < 4; ks++) {
            int k0 = ks * 8 + (lane & 3);
            uint32_t af[4][4], bf[4][2];
#pragma unroll
            for (int mi = 0; mi < 4; mi++) {
                int r0 = wm * 64 + mi * 16 + (lane >> 2);
                af[mi][0] = __float_as_uint(As_[r0 * 36 + k0]);
                af[mi][1] = __float_as_uint(As_[(r0 + 8) * 36 + k0]);
                af[mi][2] = __float_as_uint(As_[r0 * 36 + k0 + 4]);
                af[mi][3] = __float_as_uint(As_[(r0 + 8) * 36 + k0 + 4]);
            }
#pragma unroll
            for (int ni = 0; ni < 4; ni++) {
                int c0 = wn * 32 + ni * 8 + (lane >> 2);
                bf[ni][0] = __float_as_uint(Bs_[c0 * 36 + k0]);
                bf[ni][1] = __float_as_uint(Bs_[c0 * 36 + k0 + 4]);
            }
#pragma unroll
            for (int mi = 0; mi < 4; mi++)
#pragma unroll
                for (int ni = 0; ni < 4; ni++) mma_tf32(acc[mi][ni], af[mi], bf[ni]);
        }
        __syncthreads();
    }

    // ---- epilogue: stage C tile (128g x 128n, pad 132) in smem, then coalesced float4 sweep ----
    float* sC = smem;   // 128*132 floats = 67584 B <= 73728 B allocated
#pragma unroll
    for (int mi = 0; mi < 4; mi++)
#pragma unroll
        for (int ni = 0; ni < 4; ni++)
#pragma unroll
            for (int rr = 0; rr < 2; rr++) {
                int gl = wm * 64 + mi * 16 + (lane >> 2) + rr * 8;
                int nl = wn * 32 + ni * 8 + 2 * (lane & 3);
                *reinterpret_cast<float2*>(&sC[gl * 132 + nl]) =
                    make_float2(acc[mi][ni][rr * 2 + 0], acc[mi][ni][rr * 2 + 1]);
            }
    __syncthreads();

    const int t0 = bx * 4;
    const size_t dbase = (size_t)dir * TT * (size_t)(G3 * BATCH);
#pragma unroll
    for (int k2 = 0; k2 < 16; k2++) {
        int idx = tid + 256 * k2;
        int g  = idx >> 5;          // 0..127
        int n4 = idx & 31;          // float4 index within 128 n-cols
        int tl = n4 >> 3;           // 0..3  (t within tile)
        int b  = (n4 & 7) * 4;      // 0..28
        float4 v = *reinterpret_cast<const float4*>(&sC[g * 132 + n4 * 4]);
        float bias = bih[by * 128 + g];
        v.x += bias; v.y += bias; v.z += bias; v.w += bias;
        size_t off = dbase + (size_t)(t0 + tl) * (G3 * BATCH) + (size_t)(by * 128 + g) * BATCH + b;
        *reinterpret_cast<float4*>(d_xp + off) = v;
    }

    // publish this (dir, time-block) tile: counter reaches 12 when whole block ready
    __syncthreads();
    if (tid == 0) {
        __threadfence();
        atomicAdd(&d_gsync[dir * 256 + bx], 1u);
    }
}

// ---------------- kernel 3: persistent recurrence, dataflow-synced, staged loads ----------------
#define REC_SMEM_FLOATS (12288 + 16384 + 3072 + 48)
#define REC_SMEM_BYTES  (REC_SMEM_FLOATS * 4)

__global__ void __launch_bounds__(256, 1)
rec_kernel(const float* __restrict__ bhhf, const float* __restrict__ bhhb,
           float* __restrict__ out) {
    extern __shared__ float smf[];
    float2* sRed2 = reinterpret_cast<float2*>(smf);   // [w][mi][ni][rr][lane] float2
    float*  sB    = smf + 12288;                       // h(s) image, fragment order
    float*  sXp   = smf + 12288 + 16384;               // [2][48][32]
    float*  sBias = sXp + 3072;

    const int c = blockIdx.x, dir = blockIdx.y;
    const int tid = threadIdx.x, lane = tid & 31, w = tid >> 5;
    const int c16 = c * 16;

    // register-resident W fragments: warp w owns kk = 8w .. 8w+7
    float4 aw[8][3];
    {
        const float4* wsrc = reinterpret_cast<const float4*>(
            d_whpf + ((size_t)(dir * NCTA_PER_DIR + c)) * 64 * 384);
#pragma unroll
        for (int q = 0; q < 8; q++)
#pragma unroll
            for (int mi = 0; mi < 3; mi++)
                aw[q][mi] = wsrc[((w * 8 + q) * 3 + mi) * 32 + lane];
    }
    if (tid < 48) sBias[tid] = (dir ? bhhb : bhhf)[gate_row(c, tid)];
    __syncthreads();

    float* hbase = d_h + (size_t)dir * 4 * 16384;
    unsigned* f1 = d_f1 + dir * 1024;                   // [cta][32-pad]
    const unsigned* gcnt = d_gsync + dir * 256;         // gemm progress counters
    int gb_seen = -1;

    // prologue: wait for gemm block of t0, then prefetch xp(0) into buf 0
    {
        const int t0 = dir ? (TT - 1) : 0;
        const int tb0 = t0 >> 2;
        while (ldacq(gcnt + tb0) < 12u) {}
        gb_seen = tb0;
        const float* xps = d_xp + ((size_t)dir * TT + t0) * (size_t)(G3 * BATCH);
        for (int o = tid; o < 384; o += 256) {
            int j = o >> 3, seg = o & 7;
            cp16(&sXp[(j * 32 + seg * 4)], xps + (size_t)gate_row(c, j) * BATCH + seg * 4);
        }
        cp_commit();
    }

    const int we_ni = w & 3, we_rr = w >> 2;

    for (int s = 0; s < TT; s++) {
        const int t = dir ? (TT - 1 - s) : s;
        const float* hrd = hbase + (size_t)(s & 3) * 16384;
        float* hwr = hbase + (size_t)((s + 1) & 3) * 16384;

        // per-warp: wait for my 4 source CTAs (dual-phase: 2 poll streams per flag)
        if (s > 0) {
            if (lane < 8) {
                const unsigned* fp = f1 + (4 * w + (lane & 3)) * 32;
                unsigned bal;
                do {
                    unsigned v = ldacq(fp);
                    bal = __ballot_sync(0x000000FFu, v >= (unsigned)s);
                    bal |= bal >> 4;
                } while ((bal & 0xFu) != 0xFu);
            }
            __syncwarp();
        }
        // my 8KB h chunk: asymmetric groups A=2KB (q0-1), B=6KB (q2-7)
        {
            const float* src = hrd + w * 2048;
            float* dst = sB + w * 2048;
#pragma unroll
            for (int r = 0; r < 4; r++)
                cp16(dst + (lane + r * 32) * 4, src + (lane + r * 32) * 4);
            cp_commit();
#pragma unroll
            for (int r = 4; r < 16; r++)
                cp16(dst + (lane + r * 32) * 4, src + (lane + r * 32) * 4);
            cp_commit();
        }
        // prefetch xp(s+1): gate on gemm progress (register-cached, ~1 poll per 4 steps)
        {
            int tn = dir ? (TT - 2 - s) : (s + 1);
            if (tn < 0) tn = 0; if (tn >= TT) tn = TT - 1;
            int tb = tn >> 2;
            if (tb != gb_seen) {
                while (ldacq(gcnt + tb) < 12u) {}
                gb_seen = tb;
            }
            const float* xps = d_xp + ((size_t)dir * TT + tn) * (size_t)(G3 * BATCH);
            float* dst = sXp + ((s + 1) & 1) * 1536;
            for (int o = tid; o < 384; o += 256) {
                int j = o >> 3, seg = o & 7;
                cp16(dst + j * 32 + seg * 4, xps + (size_t)gate_row(c, j) * BATCH + seg * 4);
            }
            cp_commit();
        }
        // pending now: xp(s), A(s), B(s), xp(s+1)

        float acc[3][4][4];
#pragma unroll
        for (int mi = 0; mi < 3; mi++)
#pragma unroll
            for (int ni = 0; ni < 4; ni++)
#pragma unroll
                for (int k = 0; k < 4; k++) acc[mi][ni][k] = 0.f;

        cp_wait<2>();   // xp(s) + A done; B + xp(s+1) in flight
        __syncwarp();
#pragma unroll
        for (int q = 0; q < 2; q++) {
            const int base = (w * 8 + q) * 256 + (lane >> 2) * 8 + (lane & 3) * 2;
            float2 bf[4];
#pragma unroll
            for (int ni = 0; ni < 4; ni++)
                bf[ni] = *reinterpret_cast<const float2*>(&sB[base + ni * 64]);
#pragma unroll
            for (int mi = 0; mi < 3; mi++)
#pragma unroll
                for (int ni = 0; ni < 4; ni++)
                    mma_tf32_f(acc[mi][ni], aw[q][mi], bf[ni]);
        }
        cp_wait<1>();   // B done; xp(s+1) in flight
        __syncwarp();
#pragma unroll
        for (int q = 2; q < 8; q++) {
            const int base = (w * 8 + q) * 256 + (lane >> 2) * 8 + (lane & 3) * 2;
            float2 bf[4];
#pragma unroll
            for (int ni = 0; ni < 4; ni++)
                bf[ni] = *reinterpret_cast<const float2*>(&sB[base + ni * 64]);
#pragma unroll
            for (int mi = 0; mi < 3; mi++)
#pragma unroll
                for (int ni = 0; ni < 4; ni++)
                    mma_tf32_f(acc[mi][ni], aw[q][mi], bf[ni]);
        }

        // partials: [w][mi][ni][rr][lane] float2
#pragma unroll
        for (int mi = 0; mi < 3; mi++)
#pragma unroll
            for (int ni = 0; ni < 4; ni++) {
                sRed2[(((w * 3 + mi) * 4 + ni) * 2 + 0) * 32 + lane] =
                    make_float2(acc[mi][ni][0], acc[mi][ni][1]);
                sRed2[(((w * 3 + mi) * 4 + ni) * 2 + 1) * 32 + lane] =
                    make_float2(acc[mi][ni][2], acc[mi][ni][3]);
            }
        __syncthreads();   // sync1: partials visible; all global h(s) reads complete

        // epilogue, all 8 warps: ni=we_ni, row-half=we_rr -> 2 elements/thread
        float esum[3][2];
#pragma unroll
        for (int mi = 0; mi < 3; mi++) {
            float2 a0 = sRed2[(((0 * 3 + mi) * 4 + we_ni) * 2 + we_rr) * 32 + lane];
#pragma unroll
            for (int ww = 1; ww < 8; ww++) {
                float2 p = sRed2[(((ww * 3 + mi) * 4 + we_ni) * 2 + we_rr) * 32 + lane];
                a0.x += p.x; a0.y += p.y;
            }
            esum[mi][0] = a0.x; esum[mi][1] = a0.y;
        }
        const int row = we_rr * 8 + (lane >> 2);
        const int kg = c16 + row;
        const float* xpb = sXp + (s & 1) * 1536;
        float hnew2[2];
#pragma unroll
        for (int cc = 0; cc < 2; cc++) {
            int b = we_ni * 8 + 2 * (lane & 3) + cc;
            float rpre = esum[0][cc] + sBias[row];
            float zpre = esum[1][cc] + sBias[16 + row];
            float npre = esum[2][cc] + sBias[32 + row];
            float xr  = xpb[row * 32 + b];
            float xz  = xpb[(16 + row) * 32 + b];
            float xnv = xpb[(32 + row) * 32 + b];
            float rg = 1.0f / (1.0f + __expf(-(xr + rpre)));
            float zg = 1.0f / (1.0f + __expf(-(xz + zpre)));
            float narg = xnv + rg * npre;
            float ng = 2.0f / (1.0f + __expf(-2.0f * narg)) - 1.0f;   // tanh
            int hoff = (kg >> 3) * 256 + b * 8 + (kg & 3) * 2 + ((kg >> 2) & 1);
            float hold = sB[hoff];
            float hnew = (1.0f - zg) * ng + zg * hold;
            hwr[hoff] = hnew;
            hnew2[cc] = hnew;
        }
        __syncthreads();   // sync2: all h(s+1) stores issued (CTA-visible)
        if (tid == 0) {
            __threadfence();                                    // single-thread release (cumulative)
            strlx(f1 + c * 32, (unsigned)(s + 1));              // publish h(s+1)
        }

        // GELU + output (off the critical path)
#pragma unroll
        for (int cc = 0; cc < 2; cc++) {
            int b = we_ni * 8 + 2 * (lane & 3) + cc;
            float hnew = hnew2[cc];
            float g = 0.5f * hnew * (1.0f + erff(hnew * 0.70710678118f));
            out[((size_t)b * TT + t) * (size_t)(2 * HH) + (size_t)dir * HH + kg] = g;
        }
    }
}

// ---------------- launcher ----------------
extern "C" void kernel_launch(void* const* d_in, const int* in_sizes, int n_in,
                              void* d_out, int out_size) {
    const float* x       = (const float*)d_in[0];
    const float* ln_g    = (const float*)d_in[1];
    const float* ln_b    = (const float*)d_in[2];
    const float* w_ih_f  = (const float*)d_in[3];
    const float* w_hh_f  = (const float*)d_in[4];
    const float* b_ih_f  = (const float*)d_in[5];
    const float* b_hh_f  = (const float*)d_in[6];
    const float* w_ih_b  = (const float*)d_in[7];
    const float* w_hh_b  = (const float*)d_in[8];
    const float* b_ih_b  = (const float*)d_in[9];
    const float* b_hh_b  = (const float*)d_in[10];
    float* out = (float*)d_out;

    static cudaStream_t s2 = nullptr;
    static cudaEvent_t evFork = nullptr, evJoin = nullptr;
    if (!s2) {
        cudaStreamCreateWithFlags(&s2, cudaStreamNonBlocking);
        cudaEventCreateWithFlags(&evFork, cudaEventDisableTiming);
        cudaEventCreateWithFlags(&evJoin, cudaEventDisableTiming);
        cudaFuncSetAttribute(gemm_kernel, cudaFuncAttributeMaxDynamicSharedMemorySize,
                             4 * GEMM_BUF_FLOATS * 4);
        cudaFuncSetAttribute(rec_kernel, cudaFuncAttributeMaxDynamicSharedMemorySize,
                             REC_SMEM_BYTES);
    }

    prep_kernel<<<2048, 256>>>(w_ih_f, w_hh_f, w_ih_b, w_hh_b);
    ln_kernel<<<BATCH * TT, 128>>>(x, ln_g, ln_b);

    // fork: gemm runs concurrently with rec; rec self-synchronizes on d_gsync
    cudaEventRecord(evFork, 0);
    cudaStreamWaitEvent(s2, evFork, 0);
    gemm_kernel<<<dim3(12, 512, 1), 256, 4 * GEMM_BUF_FLOATS * 4, s2>>>(b_ih_f, b_ih_b);
    cudaEventRecord(evJoin, s2);

    rec_kernel<<<dim3(NCTA_PER_DIR, 2), 256, REC_SMEM_BYTES>>>(b_hh_f, b_hh_b, out);

    // join forked stream back into the capture origin
    cudaStreamWaitEvent(0, evJoin, 0);
}

// round 11
// speedup vs baseline: 1.1849x; 1.1849x over previous
#include <cuda_runtime.h>
#include <cuda_bf16.h>
#include <cstdint>
#include <cstddef>

#define BATCH 32
#define TT    1024
#define II    512
#define HH    512
#define G3    1536
#define NCTA_PER_DIR 32

// ---------------- device scratch ----------------
__device__ float d_xn[(size_t)BATCH * TT * II];
__device__ float d_xp[(size_t)2 * TT * G3 * BATCH];
__device__ float d_wA[2 * 12 * 16 * 4096];              // fragment-packed W_ih for gemm
__device__ float d_whpf[2 * NCTA_PER_DIR * 64 * 384];   // fragment-packed W_hh for rec
__device__ float d_h[2 * 4 * 16384];                    // h 4-deep ring [dir][buf][16384]
__device__ unsigned int d_f1[2 * 32 * 32];              // produce flags, 128B padded

// ---------------- helpers ----------------
__device__ __forceinline__ float tf32r(float x) {
    uint32_t u; asm("cvt.rna.tf32.f32 %0, %1;" : "=r"(u) : "f"(x));
    return __uint_as_float(u);
}
__device__ __forceinline__ void cp16(void* smem_dst, const void* gmem_src) {
    uint32_t s = (uint32_t)__cvta_generic_to_shared(smem_dst);
    asm volatile("cp.async.cg.shared.global [%0], [%1], 16;" :: "r"(s), "l"(gmem_src));
}
__device__ __forceinline__ void cp_commit() { asm volatile("cp.async.commit_group;"); }
template <int N> __device__ __forceinline__ void cp_wait() {
    asm volatile("cp.async.wait_group %0;" :: "n"(N));
}
__device__ __forceinline__ unsigned ldacq(const unsigned* p) {
    unsigned v; asm volatile("ld.acquire.gpu.global.u32 %0, [%1];" : "=r"(v) : "l"(p)); return v;
}
__device__ __forceinline__ void strlx(unsigned* p, unsigned v) {
    asm volatile("st.relaxed.gpu.global.u32 [%0], %1;" :: "l"(p), "r"(v));
}
__device__ __forceinline__ void mma_tf32_ab(float* d, const float4& a, uint32_t b0, uint32_t b1) {
    asm volatile(
        "mma.sync.aligned.m16n8k8.row.col.f32.tf32.tf32.f32 "
        "{%0,%1,%2,%3},{%4,%5,%6,%7},{%8,%9},{%0,%1,%2,%3};"
        : "+f"(d[0]), "+f"(d[1]), "+f"(d[2]), "+f"(d[3])
        : "r"(__float_as_uint(a.x)), "r"(__float_as_uint(a.y)),
          "r"(__float_as_uint(a.z)), "r"(__float_as_uint(a.w)),
          "r"(b0), "r"(b1));
}
__device__ __forceinline__ void mma_tf32_f(float* d, const float4& a, const float2& b) {
    asm volatile(
        "mma.sync.aligned.m16n8k8.row.col.f32.tf32.tf32.f32 "
        "{%0,%1,%2,%3},{%4,%5,%6,%7},{%8,%9},{%0,%1,%2,%3};"
        : "+f"(d[0]), "+f"(d[1]), "+f"(d[2]), "+f"(d[3])
        : "r"(__float_as_uint(a.x)), "r"(__float_as_uint(a.y)),
          "r"(__float_as_uint(a.z)), "r"(__float_as_uint(a.w)),
          "r"(__float_as_uint(b.x)), "r"(__float_as_uint(b.y)));
}
__device__ __forceinline__ int gate_row(int c, int j) {
    return (j < 16) ? (c * 16 + j)
         : (j < 32) ? (512 + c * 16 + (j - 16))
                    : (1024 + c * 16 + (j - 32));
}

// ---------------- kernel 0: prep ----------------
__global__ void prep_kernel(const float* __restrict__ wihf, const float* __restrict__ whhf,
                            const float* __restrict__ wihb, const float* __restrict__ whhb) {
    int idx = blockIdx.x * blockDim.x + threadIdx.x;
    int stride = gridDim.x * blockDim.x;
    // fragment-packed W_ih: [dir][by][kb][(wm*4+mi)*4+ks][lane][reg]
    for (int i = idx; i < 2 * 12 * 16 * 4096; i += stride) {
        int tmp = i;
        int reg  = tmp & 3;  tmp >>= 2;
        int lane = tmp & 31; tmp >>= 5;
        int m32  = tmp & 31; tmp >>= 5;
        int kb   = tmp & 15; tmp >>= 4;
        int by   = tmp % 12;
        int dir  = tmp / 12;
        int ks = m32 & 3, mi = (m32 >> 2) & 3, wm = m32 >> 4;
        int g = by * 128 + wm * 64 + mi * 16 + (lane >> 2) + (reg & 1) * 8;
        int k = kb * 32 + ks * 8 + (lane & 3) + (reg >> 1) * 4;
        const float* w = dir ? wihb : wihf;
        d_wA[i] = tf32r(w[g * II + k]);
    }
    // fragment-packed W_hh: [dir][c][kk][mi][lane][reg]
    for (int i = idx; i < 2 * NCTA_PER_DIR * 64 * 384; i += stride) {
        int reg  = i & 3;
        int lane = (i >> 2) & 31;
        int mi   = (i % 384) / 128;
        int kk   = (i / 384) & 63;
        int c    = (i / (384 * 64)) % NCTA_PER_DIR;
        int dir  = i / (384 * 64 * NCTA_PER_DIR);
        int j = mi * 16 + (lane >> 2) + 8 * (reg & 1);
        int k = kk * 8 + (lane & 3) + 4 * (reg >> 1);
        const float* w = dir ? whhb : whhf;
        d_whpf[i] = tf32r(w[gate_row(c, j) * II + k]);
    }
    for (int i = idx; i < 2 * 4 * 16384; i += stride) d_h[i] = 0.0f;
    for (int i = idx; i < 2 * 32 * 32; i += stride) d_f1[i] = 0u;
}

// ---------------- kernel 1: LayerNorm ----------------
__global__ void ln_kernel(const float* __restrict__ x, const float* __restrict__ gamma,
                          const float* __restrict__ beta) {
    int row = blockIdx.x;
    const float* xr = x + (size_t)row * II;
    int tid = threadIdx.x;
    float v[4]; float s = 0.f, q = 0.f;
#pragma unroll
    for (int k = 0; k < 4; k++) {
        v[k] = xr[tid + 128 * k];
        s += v[k]; q += v[k] * v[k];
    }
#pragma unroll
    for (int o = 16; o > 0; o >>= 1) {
        s += __shfl_xor_sync(0xffffffffu, s, o);
        q += __shfl_xor_sync(0xffffffffu, q, o);
    }
    __shared__ float ws[4], wq[4];
    if ((tid & 31) == 0) { ws[tid >> 5] = s; wq[tid >> 5] = q; }
    __syncthreads();
    s = ws[0] + ws[1] + ws[2] + ws[3];
    q = wq[0] + wq[1] + wq[2] + wq[3];
    float mu = s * (1.0f / 512.0f);
    float var = q * (1.0f / 512.0f) - mu * mu;
    float rstd = rsqrtf(var + 1e-5f);
#pragma unroll
    for (int k = 0; k < 4; k++) {
        int i = tid + 128 * k;
        d_xn[(size_t)row * II + i] = tf32r((v[k] - mu) * rstd * gamma[i] + beta[i]);
    }
}

// ---------------- kernel 2: input-projection GEMM (fragment-packed A, LDS.128) ----------------
// smem: As 2 x 4096 floats | Bs 2 x 4608 floats ; epilogue reuses as sC 128x132
#define GEMM_SMEM_BYTES 73728
__global__ void __launch_bounds__(256)
gemm_kernel(const float* __restrict__ bihf, const float* __restrict__ bihb) {
    extern __shared__ float smem[];
    float* As = smem;                 // 2 bufs x 4096 (fragment-packed)
    float* Bs = smem + 8192;          // 2 bufs x 4608 (128 cols x 36)
    int bx = blockIdx.x, by = blockIdx.y, dir = blockIdx.z;
    int tid = threadIdx.x, lane = tid & 31, wid = tid >> 5;
    int wm = wid & 1, wn = wid >> 1;
    const float* bih = dir ? bihb : bihf;
    const float* Afrag = d_wA + ((size_t)(dir * 12 + by)) * 16 * 4096;

    auto load_tiles = [&](int kb, int buf) {
        float* As_ = As + buf * 4096;
        float* Bs_ = Bs + buf * 4608;
        const float* asrc = Afrag + kb * 4096;
#pragma unroll
        for (int u = 0; u < 4; u++) {
            int o = tid + 256 * u;
            cp16(&As_[o * 4], asrc + o * 4);
        }
#pragma unroll
        for (int u = 0; u < 4; u++) {
            int o = tid + 256 * u;
            int col = o >> 3, seg = o & 7;
            int n = bx * 128 + col;
            int t = n >> 5, b = n & 31;
            cp16(&Bs_[col * 36 + seg * 4], d_xn + ((size_t)b * TT + t) * II + kb * 32 + seg * 4);
        }
    };

    float acc[4][4][4];
#pragma unroll
    for (int i = 0; i < 4; i++)
#pragma unroll
        for (int j = 0; j < 4; j++)
#pragma unroll
            for (int k = 0; k < 4; k++) acc[i][j][k] = 0.f;

    load_tiles(0, 0); cp_commit();
    for (int kb = 0; kb < 16; kb++) {
        if (kb + 1 < 16) { load_tiles(kb + 1, (kb + 1) & 1); cp_commit(); cp_wait<1>(); }
        else cp_wait<0>();
        __syncthreads();
        const float4* As4 = reinterpret_cast<const float4*>(As + (kb & 1) * 4096);
        float* Bs_ = Bs + (kb & 1) * 4608;
#pragma unroll
        for (int ks = 0; ks < 4; ks++) {
            int k0 = ks * 8 + (lane & 3);
            float4 af[4];
            uint32_t bf[4][2];
#pragma unroll
            for (int mi = 0; mi < 4; mi++)
                af[mi] = As4[((wm * 4 + mi) * 4 + ks) * 32 + lane];
#pragma unroll
            for (int ni = 0; ni < 4; ni++) {
                int c0 = wn * 32 + ni * 8 + (lane >> 2);
                bf[ni][0] = __float_as_uint(Bs_[c0 * 36 + k0]);
                bf[ni][1] = __float_as_uint(Bs_[c0 * 36 + k0 + 4]);
            }
#pragma unroll
            for (int mi = 0; mi < 4; mi++)
#pragma unroll
                for (int ni = 0; ni < 4; ni++)
                    mma_tf32_ab(acc[mi][ni], af[mi], bf[ni][0], bf[ni][1]);
        }
        __syncthreads();
    }

    // ---- epilogue: stage C tile (128g x 128n, pad 132) in smem, then coalesced float4 sweep ----
    float* sC = smem;   // 128*132 floats = 67584 B <= 73728 B allocated
#pragma unroll
    for (int mi = 0; mi < 4; mi++)
#pragma unroll
        for (int ni = 0; ni < 4; ni++)
#pragma unroll
            for (int rr = 0; rr < 2; rr++) {
                int gl = wm * 64 + mi * 16 + (lane >> 2) + rr * 8;
                int nl = wn * 32 + ni * 8 + 2 * (lane & 3);
                *reinterpret_cast<float2*>(&sC[gl * 132 + nl]) =
                    make_float2(acc[mi][ni][rr * 2 + 0], acc[mi][ni][rr * 2 + 1]);
            }
    __syncthreads();

    const int t0 = bx * 4;
    const size_t dbase = (size_t)dir * TT * (size_t)(G3 * BATCH);
#pragma unroll
    for (int k2 = 0; k2 < 16; k2++) {
        int idx = tid + 256 * k2;
        int g  = idx >> 5;
        int n4 = idx & 31;
        int tl = n4 >> 3;
        int b  = (n4 & 7) * 4;
        float4 v = *reinterpret_cast<const float4*>(&sC[g * 132 + n4 * 4]);
        float bias = bih[by * 128 + g];
        v.x += bias; v.y += bias; v.z += bias; v.w += bias;
        size_t off = dbase + (size_t)(t0 + tl) * (G3 * BATCH) + (size_t)(by * 128 + g) * BATCH + b;
        *reinterpret_cast<float4*>(d_xp + off) = v;
    }
}

// ---------------- kernel 3: persistent recurrence (Round-8 form, best measured) ----------------
#define REC_SMEM_FLOATS (12288 + 16384 + 3072 + 48)
#define REC_SMEM_BYTES  (REC_SMEM_FLOATS * 4)

__global__ void __launch_bounds__(256, 1)
rec_kernel(const float* __restrict__ bhhf, const float* __restrict__ bhhb,
           float* __restrict__ out) {
    extern __shared__ float smf[];
    float2* sRed2 = reinterpret_cast<float2*>(smf);   // [w][mi][ni][rr][lane] float2
    float*  sB    = smf + 12288;                       // h(s) image, fragment order
    float*  sXp   = smf + 12288 + 16384;               // [2][48][32]
    float*  sBias = sXp + 3072;

    const int c = blockIdx.x, dir = blockIdx.y;
    const int tid = threadIdx.x, lane = tid & 31, w = tid >> 5;
    const int c16 = c * 16;

    float4 aw[8][3];
    {
        const float4* wsrc = reinterpret_cast<const float4*>(
            d_whpf + ((size_t)(dir * NCTA_PER_DIR + c)) * 64 * 384);
#pragma unroll
        for (int q = 0; q < 8; q++)
#pragma unroll
            for (int mi = 0; mi < 3; mi++)
                aw[q][mi] = wsrc[((w * 8 + q) * 3 + mi) * 32 + lane];
    }
    if (tid < 48) sBias[tid] = (dir ? bhhb : bhhf)[gate_row(c, tid)];
    __syncthreads();

    float* hbase = d_h + (size_t)dir * 4 * 16384;
    unsigned* f1 = d_f1 + dir * 1024;

    {
        const int t0 = dir ? (TT - 1) : 0;
        const float* xps = d_xp + ((size_t)dir * TT + t0) * (size_t)(G3 * BATCH);
        for (int o = tid; o < 384; o += 256) {
            int j = o >> 3, seg = o & 7;
            cp16(&sXp[(j * 32 + seg * 4)], xps + (size_t)gate_row(c, j) * BATCH + seg * 4);
        }
        cp_commit();
    }

    const int we_ni = w & 3, we_rr = w >> 2;

    for (int s = 0; s < TT; s++) {
        const int t = dir ? (TT - 1 - s) : s;
        const float* hrd = hbase + (size_t)(s & 3) * 16384;
        float* hwr = hbase + (size_t)((s + 1) & 3) * 16384;

        if (s > 0) {
            const unsigned* fp = f1 + (4 * w + (lane & 3)) * 32;
            unsigned v;
            do { v = ldacq(fp); } while (__any_sync(0xffffffffu, v < (unsigned)s));
        }
        {
            const float* src = hrd + w * 2048;
            float* dst = sB + w * 2048;
#pragma unroll
            for (int r = 0; r < 8; r++)
                cp16(dst + (lane + r * 32) * 4, src + (lane + r * 32) * 4);
            cp_commit();
#pragma unroll
            for (int r = 8; r < 16; r++)
                cp16(dst + (lane + r * 32) * 4, src + (lane + r * 32) * 4);
            cp_commit();
        }
        {
            int tn = dir ? (TT - 2 - s) : (s + 1);
            if (tn < 0) tn = 0; if (tn >= TT) tn = TT - 1;
            const float* xps = d_xp + ((size_t)dir * TT + tn) * (size_t)(G3 * BATCH);
            float* dst = sXp + ((s + 1) & 1) * 1536;
            for (int o = tid; o < 384; o += 256) {
                int j = o >> 3, seg = o & 7;
                cp16(dst + j * 32 + seg * 4, xps + (size_t)gate_row(c, j) * BATCH + seg * 4);
            }
            cp_commit();
        }

        float acc[3][4][4];
#pragma unroll
        for (int mi = 0; mi < 3; mi++)
#pragma unroll
            for (int ni = 0; ni < 4; ni++)
#pragma unroll
                for (int k = 0; k < 4; k++) acc[mi][ni][k] = 0.f;

        cp_wait<2>();
        __syncwarp();
#pragma unroll
        for (int q = 0; q < 4; q++) {
            const int base = (w * 8 + q) * 256 + (lane >> 2) * 8 + (lane & 3) * 2;
            float2 bf[4];
#pragma unroll
            for (int ni = 0; ni < 4; ni++)
                bf[ni] = *reinterpret_cast<const float2*>(&sB[base + ni * 64]);
#pragma unroll
            for (int mi = 0; mi < 3; mi++)
#pragma unroll
                for (int ni = 0; ni < 4; ni++)
                    mma_tf32_f(acc[mi][ni], aw[q][mi], bf[ni]);
        }
        cp_wait<1>();
        __syncwarp();
#pragma unroll
        for (int q = 4; q < 8; q++) {
            const int base = (w * 8 + q) * 256 + (lane >> 2) * 8 + (lane & 3) * 2;
            float2 bf[4];
#pragma unroll
            for (int ni = 0; ni < 4; ni++)
                bf[ni] = *reinterpret_cast<const float2*>(&sB[base + ni * 64]);
#pragma unroll
            for (int mi = 0; mi < 3; mi++)
#pragma unroll
                for (int ni = 0; ni < 4; ni++)
                    mma_tf32_f(acc[mi][ni], aw[q][mi], bf[ni]);
        }

#pragma unroll
        for (int mi = 0; mi < 3; mi++)
#pragma unroll
            for (int ni = 0; ni < 4; ni++) {
                sRed2[(((w * 3 + mi) * 4 + ni) * 2 + 0) * 32 + lane] =
                    make_float2(acc[mi][ni][0], acc[mi][ni][1]);
                sRed2[(((w * 3 + mi) * 4 + ni) * 2 + 1) * 32 + lane] =
                    make_float2(acc[mi][ni][2], acc[mi][ni][3]);
            }
        __syncthreads();   // sync1

        float esum[3][2];
#pragma unroll
        for (int mi = 0; mi < 3; mi++) {
            float2 a0 = sRed2[(((0 * 3 + mi) * 4 + we_ni) * 2 + we_rr) * 32 + lane];
#pragma unroll
            for (int ww = 1; ww < 8; ww++) {
                float2 p = sRed2[(((ww * 3 + mi) * 4 + we_ni) * 2 + we_rr) * 32 + lane];
                a0.x += p.x; a0.y += p.y;
            }
            esum[mi][0] = a0.x; esum[mi][1] = a0.y;
        }
        const int row = we_rr * 8 + (lane >> 2);
        const int kg = c16 + row;
        const float* xpb = sXp + (s & 1) * 1536;
        float hnew2[2];
#pragma unroll
        for (int cc = 0; cc < 2; cc++) {
            int b = we_ni * 8 + 2 * (lane & 3) + cc;
            float rpre = esum[0][cc] + sBias[row];
            float zpre = esum[1][cc] + sBias[16 + row];
            float npre = esum[2][cc] + sBias[32 + row];
            float xr  = xpb[row * 32 + b];
            float xz  = xpb[(16 + row) * 32 + b];
            float xnv = xpb[(32 + row) * 32 + b];
            float rg = 1.0f / (1.0f + __expf(-(xr + rpre)));
            float zg = 1.0f / (1.0f + __expf(-(xz + zpre)));
            float narg = xnv + rg * npre;
            float ng = 2.0f / (1.0f + __expf(-2.0f * narg)) - 1.0f;   // tanh
            int hoff = (kg >> 3) * 256 + b * 8 + (kg & 3) * 2 + ((kg >> 2) & 1);
            float hold = sB[hoff];
            float hnew = (1.0f - zg) * ng + zg * hold;
            hwr[hoff] = hnew;
            hnew2[cc] = hnew;
        }
        __syncthreads();   // sync2
        if (tid == 0) {
            __threadfence();
            strlx(f1 + c * 32, (unsigned)(s + 1));
        }

#pragma unroll
        for (int cc = 0; cc < 2; cc++) {
            int b = we_ni * 8 + 2 * (lane & 3) + cc;
            float hnew = hnew2[cc];
            float g = 0.5f * hnew * (1.0f + erff(hnew * 0.70710678118f));
            out[((size_t)b * TT + t) * (size_t)(2 * HH) + (size_t)dir * HH + kg] = g;
        }
    }
}

// ---------------- launcher ----------------
extern "C" void kernel_launch(void* const* d_in, const int* in_sizes, int n_in,
                              void* d_out, int out_size) {
    const float* x       = (const float*)d_in[0];
    const float* ln_g    = (const float*)d_in[1];
    const float* ln_b    = (const float*)d_in[2];
    const float* w_ih_f  = (const float*)d_in[3];
    const float* w_hh_f  = (const float*)d_in[4];
    const float* b_ih_f  = (const float*)d_in[5];
    const float* b_hh_f  = (const float*)d_in[6];
    const float* w_ih_b  = (const float*)d_in[7];
    const float* w_hh_b  = (const float*)d_in[8];
    const float* b_ih_b  = (const float*)d_in[9];
    const float* b_hh_b  = (const float*)d_in[10];
    float* out = (float*)d_out;

    static bool attr_done = false;
    if (!attr_done) {
        cudaFuncSetAttribute(gemm_kernel, cudaFuncAttributeMaxDynamicSharedMemorySize,
                             GEMM_SMEM_BYTES);
        cudaFuncSetAttribute(rec_kernel, cudaFuncAttributeMaxDynamicSharedMemorySize,
                             REC_SMEM_BYTES);
        attr_done = true;
    }

    prep_kernel<<<2048, 256>>>(w_ih_f, w_hh_f, w_ih_b, w_hh_b);
    ln_kernel<<<BATCH * TT, 128>>>(x, ln_g, ln_b);
    gemm_kernel<<<dim3(256, 12, 2), 256, GEMM_SMEM_BYTES>>>(b_ih_f, b_ih_b);
    rec_kernel<<<dim3(NCTA_PER_DIR, 2), 256, REC_SMEM_BYTES>>>(b_hh_f, b_hh_b, out);
}

// round 13
// speedup vs baseline: 1.3171x; 1.1116x over previous
#include <cuda_runtime.h>
#include <cuda_bf16.h>
#include <cuda_fp16.h>
#include <cstdint>
#include <cstddef>

#define BATCH 32
#define TT    1024
#define II    512
#define HH    512
#define G3    1536
#define NCTA_PER_DIR 32

// ---------------- device scratch ----------------
__device__ __half  d_xnh[(size_t)BATCH * TT * II];      // LN output (fp16), [b][t][i]
__device__ float   d_xp[(size_t)2 * TT * G3 * BATCH];
__device__ __half2 d_wAh[786432];                        // fragment-packed fp16 W_ih
__device__ float   d_whpf[2 * NCTA_PER_DIR * 64 * 384];  // fragment-packed tf32 W_hh (rec)
__device__ float   d_h[2 * 4 * 16384];                   // h 4-deep ring [dir][buf][16384]
__device__ unsigned int d_f1[2 * 32 * 32];               // produce flags, 128B padded

// ---------------- helpers ----------------
__device__ __forceinline__ float tf32r(float x) {
    uint32_t u; asm("cvt.rna.tf32.f32 %0, %1;" : "=r"(u) : "f"(x));
    return __uint_as_float(u);
}
__device__ __forceinline__ uint32_t smem_u32(const void* p) {
    return (uint32_t)__cvta_generic_to_shared(p);
}
__device__ __forceinline__ void cp16(void* smem_dst, const void* gmem_src) {
    asm volatile("cp.async.cg.shared.global [%0], [%1], 16;"
                 :: "r"(smem_u32(smem_dst)), "l"(gmem_src));
}
__device__ __forceinline__ void cp_commit() { asm volatile("cp.async.commit_group;"); }
template <int N> __device__ __forceinline__ void cp_wait() {
    asm volatile("cp.async.wait_group %0;" :: "n"(N));
}
__device__ __forceinline__ unsigned ldacq(const unsigned* p) {
    unsigned v; asm volatile("ld.acquire.gpu.global.u32 %0, [%1];" : "=r"(v) : "l"(p)); return v;
}
__device__ __forceinline__ void strlx(unsigned* p, unsigned v) {
    asm volatile("st.relaxed.gpu.global.u32 [%0], %1;" :: "l"(p), "r"(v));
}
__device__ __forceinline__ void mma_f16(float* d, const float4& a, uint32_t b0, uint32_t b1) {
    asm volatile(
        "mma.sync.aligned.m16n8k16.row.col.f32.f16.f16.f32 "
        "{%0,%1,%2,%3},{%4,%5,%6,%7},{%8,%9},{%0,%1,%2,%3};"
        : "+f"(d[0]), "+f"(d[1]), "+f"(d[2]), "+f"(d[3])
        : "r"(__float_as_uint(a.x)), "r"(__float_as_uint(a.y)),
          "r"(__float_as_uint(a.z)), "r"(__float_as_uint(a.w)),
          "r"(b0), "r"(b1));
}
__device__ __forceinline__ void mma_tf32_f(float* d, const float4& a, const float2& b) {
    asm volatile(
        "mma.sync.aligned.m16n8k8.row.col.f32.tf32.tf32.f32 "
        "{%0,%1,%2,%3},{%4,%5,%6,%7},{%8,%9},{%0,%1,%2,%3};"
        : "+f"(d[0]), "+f"(d[1]), "+f"(d[2]), "+f"(d[3])
        : "r"(__float_as_uint(a.x)), "r"(__float_as_uint(a.y)),
          "r"(__float_as_uint(a.z)), "r"(__float_as_uint(a.w)),
          "r"(__float_as_uint(b.x)), "r"(__float_as_uint(b.y)));
}
__device__ __forceinline__ int gate_row(int c, int j) {
    return (j < 16) ? (c * 16 + j)
         : (j < 32) ? (512 + c * 16 + (j - 16))
                    : (1024 + c * 16 + (j - 32));
}

// ---------------- kernel 0: prep ----------------
__global__ void prep_kernel(const float* __restrict__ wihf, const float* __restrict__ whhf,
                            const float* __restrict__ wihb, const float* __restrict__ whhb) {
    int idx = blockIdx.x * blockDim.x + threadIdx.x;
    int stride = gridDim.x * blockDim.x;
    // fragment-packed fp16 W_ih: [dir][by][kb][(wm*4+mi)*2+kstep][lane][reg(4 half2)]
    for (int i = idx; i < 786432; i += stride) {
        int tmp = i;
        int reg   = tmp & 3;  tmp >>= 2;
        int lane  = tmp & 31; tmp >>= 5;
        int idx16 = tmp & 15; tmp >>= 4;
        int kb    = tmp & 15; tmp >>= 4;
        int by    = tmp % 12;
        int dir   = tmp / 12;
        int kstep = idx16 & 1, mi = (idx16 >> 1) & 3, wm = idx16 >> 3;
        int g = by * 128 + wm * 64 + mi * 16 + (lane >> 2) + (reg & 1) * 8;
        int k = kb * 32 + kstep * 16 + (lane & 3) * 2 + (reg >> 1) * 8;
        const float* w = dir ? wihb : wihf;
        d_wAh[i] = __floats2half2_rn(w[g * II + k], w[g * II + k + 1]);
    }
    // fragment-packed tf32 W_hh (rec): [dir][c][kk][mi][lane][reg]
    for (int i = idx; i < 2 * NCTA_PER_DIR * 64 * 384; i += stride) {
        int reg  = i & 3;
        int lane = (i >> 2) & 31;
        int mi   = (i % 384) / 128;
        int kk   = (i / 384) & 63;
        int c    = (i / (384 * 64)) % NCTA_PER_DIR;
        int dir  = i / (384 * 64 * NCTA_PER_DIR);
        int j = mi * 16 + (lane >> 2) + 8 * (reg & 1);
        int k = kk * 8 + (lane & 3) + 4 * (reg >> 1);
        const float* w = dir ? whhb : whhf;
        d_whpf[i] = tf32r(w[gate_row(c, j) * II + k]);
    }
    for (int i = idx; i < 2 * 4 * 16384; i += stride) d_h[i] = 0.0f;
    for (int i = idx; i < 2 * 32 * 32; i += stride) d_f1[i] = 0u;
}

// ---------------- kernel 1: LayerNorm (fp16 output) ----------------
__global__ void ln_kernel(const float* __restrict__ x, const float* __restrict__ gamma,
                          const float* __restrict__ beta) {
    int row = blockIdx.x;
    const float* xr = x + (size_t)row * II;
    int tid = threadIdx.x;
    float v[4]; float s = 0.f, q = 0.f;
#pragma unroll
    for (int k = 0; k < 4; k++) {
        v[k] = xr[tid + 128 * k];
        s += v[k]; q += v[k] * v[k];
    }
#pragma unroll
    for (int o = 16; o > 0; o >>= 1) {
        s += __shfl_xor_sync(0xffffffffu, s, o);
        q += __shfl_xor_sync(0xffffffffu, q, o);
    }
    __shared__ float ws[4], wq[4];
    if ((tid & 31) == 0) { ws[tid >> 5] = s; wq[tid >> 5] = q; }
    __syncthreads();
    s = ws[0] + ws[1] + ws[2] + ws[3];
    q = wq[0] + wq[1] + wq[2] + wq[3];
    float mu = s * (1.0f / 512.0f);
    float var = q * (1.0f / 512.0f) - mu * mu;
    float rstd = rsqrtf(var + 1e-5f);
#pragma unroll
    for (int k = 0; k < 4; k++) {
        int i = tid + 128 * k;
        d_xnh[(size_t)row * II + i] = __float2half_rn((v[k] - mu) * rstd * gamma[i] + beta[i]);
    }
}

// ---------------- kernel 2: input-projection GEMM (fp16 m16n8k16) ----------------
// smem: A bufs 2x8192B @0/@8192; B bufs 2x10240B @16384/@26624 (stride 40 halves);
// epilogue reuses smem as sC 128x132 floats.
#define GEMM_SMEM_BYTES 73728
__global__ void __launch_bounds__(256)
gemm_kernel(const float* __restrict__ bihf, const float* __restrict__ bihb) {
    extern __shared__ char smem[];
    int bx = blockIdx.x, by = blockIdx.y, dir = blockIdx.z;
    int tid = threadIdx.x, lane = tid & 31, wid = tid >> 5;
    int wm = wid & 1, wn = wid >> 1;
    const float* bih = dir ? bihb : bihf;
    const char* Abase = reinterpret_cast<const char*>(d_wAh) +
                        ((size_t)((dir * 12 + by) * 16)) * 8192;

    auto load_tiles = [&](int kb, int buf) {
        char* Ab = smem + buf * 8192;
        const char* asrc = Abase + (size_t)kb * 8192;
#pragma unroll
        for (int u = 0; u < 2; u++) {
            int o = tid + 256 * u;            // 0..511
            cp16(Ab + o * 16, asrc + o * 16);
        }
        char* Bb = smem + 16384 + buf * 10240;
#pragma unroll
        for (int u = 0; u < 2; u++) {
            int o = tid + 256 * u;            // 0..511
            int col = o >> 2, seg = o & 3;
            int n = bx * 128 + col;
            int t = n >> 5, b = n & 31;
            cp16(Bb + col * 80 + seg * 16,
                 d_xnh + ((size_t)b * TT + t) * II + kb * 32 + seg * 8);
        }
    };

    float acc[4][4][4];
#pragma unroll
    for (int i = 0; i < 4; i++)
#pragma unroll
        for (int j = 0; j < 4; j++)
#pragma unroll
            for (int k = 0; k < 4; k++) acc[i][j][k] = 0.f;

    load_tiles(0, 0); cp_commit();
    for (int kb = 0; kb < 16; kb++) {
        if (kb + 1 < 16) { load_tiles(kb + 1, (kb + 1) & 1); cp_commit(); cp_wait<1>(); }
        else cp_wait<0>();
        __syncthreads();
        const float4* As4 = reinterpret_cast<const float4*>(smem + (kb & 1) * 8192);
        const __half* Bs_ = reinterpret_cast<const __half*>(smem + 16384 + (kb & 1) * 10240);
#pragma unroll
        for (int kstep = 0; kstep < 2; kstep++) {
            float4 af[4];
            uint32_t bf[4][2];
#pragma unroll
            for (int mi = 0; mi < 4; mi++)
                af[mi] = As4[((wm * 4 + mi) * 2 + kstep) * 32 + lane];
#pragma unroll
            for (int ni = 0; ni < 4; ni++) {
                int c0 = wn * 32 + ni * 8 + (lane >> 2);
                const __half* bp = Bs_ + c0 * 40 + kstep * 16 + (lane & 3) * 2;
                bf[ni][0] = *reinterpret_cast<const uint32_t*>(bp);
                bf[ni][1] = *reinterpret_cast<const uint32_t*>(bp + 8);
            }
#pragma unroll
            for (int mi = 0; mi < 4; mi++)
#pragma unroll
                for (int ni = 0; ni < 4; ni++)
                    mma_f16(acc[mi][ni], af[mi], bf[ni][0], bf[ni][1]);
        }
        __syncthreads();
    }

    // ---- epilogue: stage C tile in smem (pad 132), coalesced float4 sweep ----
    float* sC = reinterpret_cast<float*>(smem);
#pragma unroll
    for (int mi = 0; mi < 4; mi++)
#pragma unroll
        for (int ni = 0; ni < 4; ni++)
#pragma unroll
            for (int rr = 0; rr < 2; rr++) {
                int gl = wm * 64 + mi * 16 + (lane >> 2) + rr * 8;
                int nl = wn * 32 + ni * 8 + 2 * (lane & 3);
                *reinterpret_cast<float2*>(&sC[gl * 132 + nl]) =
                    make_float2(acc[mi][ni][rr * 2 + 0], acc[mi][ni][rr * 2 + 1]);
            }
    __syncthreads();

    const int t0 = bx * 4;
    const size_t dbase = (size_t)dir * TT * (size_t)(G3 * BATCH);
#pragma unroll
    for (int k2 = 0; k2 < 16; k2++) {
        int idx = tid + 256 * k2;
        int g  = idx >> 5;
        int n4 = idx & 31;
        int tl = n4 >> 3;
        int b  = (n4 & 7) * 4;
        float4 v = *reinterpret_cast<const float4*>(&sC[g * 132 + n4 * 4]);
        float bias = bih[by * 128 + g];
        v.x += bias; v.y += bias; v.z += bias; v.w += bias;
        size_t off = dbase + (size_t)(t0 + tl) * (G3 * BATCH) + (size_t)(by * 128 + g) * BATCH + b;
        *reinterpret_cast<float4*>(d_xp + off) = v;
    }
}

// ---------------- kernel 3: persistent recurrence (best-measured form, unchanged) ----------------
#define REC_SMEM_FLOATS (12288 + 16384 + 3072 + 48)
#define REC_SMEM_BYTES  (REC_SMEM_FLOATS * 4)

__global__ void __launch_bounds__(256, 1)
rec_kernel(const float* __restrict__ bhhf, const float* __restrict__ bhhb,
           float* __restrict__ out) {
    extern __shared__ float smf[];
    float2* sRed2 = reinterpret_cast<float2*>(smf);
    float*  sB    = smf + 12288;
    float*  sXp   = smf + 12288 + 16384;
    float*  sBias = sXp + 3072;

    const int c = blockIdx.x, dir = blockIdx.y;
    const int tid = threadIdx.x, lane = tid & 31, w = tid >> 5;
    const int c16 = c * 16;

    float4 aw[8][3];
    {
        const float4* wsrc = reinterpret_cast<const float4*>(
            d_whpf + ((size_t)(dir * NCTA_PER_DIR + c)) * 64 * 384);
#pragma unroll
        for (int q = 0; q < 8; q++)
#pragma unroll
            for (int mi = 0; mi < 3; mi++)
                aw[q][mi] = wsrc[((w * 8 + q) * 3 + mi) * 32 + lane];
    }
    if (tid < 48) sBias[tid] = (dir ? bhhb : bhhf)[gate_row(c, tid)];
    __syncthreads();

    float* hbase = d_h + (size_t)dir * 4 * 16384;
    unsigned* f1 = d_f1 + dir * 1024;

    {
        const int t0 = dir ? (TT - 1) : 0;
        const float* xps = d_xp + ((size_t)dir * TT + t0) * (size_t)(G3 * BATCH);
        for (int o = tid; o < 384; o += 256) {
            int j = o >> 3, seg = o & 7;
            cp16(&sXp[(j * 32 + seg * 4)], xps + (size_t)gate_row(c, j) * BATCH + seg * 4);
        }
        cp_commit();
    }

    const int we_ni = w & 3, we_rr = w >> 2;

    for (int s = 0; s < TT; s++) {
        const int t = dir ? (TT - 1 - s) : s;
        const float* hrd = hbase + (size_t)(s & 3) * 16384;
        float* hwr = hbase + (size_t)((s + 1) & 3) * 16384;

        if (s > 0) {
            const unsigned* fp = f1 + (4 * w + (lane & 3)) * 32;
            unsigned v;
            do { v = ldacq(fp); } while (__any_sync(0xffffffffu, v < (unsigned)s));
        }
        {
            const float* src = hrd + w * 2048;
            float* dst = sB + w * 2048;
#pragma unroll
            for (int r = 0; r < 8; r++)
                cp16(dst + (lane + r * 32) * 4, src + (lane + r * 32) * 4);
            cp_commit();
#pragma unroll
            for (int r = 8; r < 16; r++)
                cp16(dst + (lane + r * 32) * 4, src + (lane + r * 32) * 4);
            cp_commit();
        }
        {
            int tn = dir ? (TT - 2 - s) : (s + 1);
            if (tn < 0) tn = 0; if (tn >= TT) tn = TT - 1;
            const float* xps = d_xp + ((size_t)dir * TT + tn) * (size_t)(G3 * BATCH);
            float* dst = sXp + ((s + 1) & 1) * 1536;
            for (int o = tid; o < 384; o += 256) {
                int j = o >> 3, seg = o & 7;
                cp16(dst + j * 32 + seg * 4, xps + (size_t)gate_row(c, j) * BATCH + seg * 4);
            }
            cp_commit();
        }

        float acc[3][4][4];
#pragma unroll
        for (int mi = 0; mi < 3; mi++)
#pragma unroll
            for (int ni = 0; ni < 4; ni++)
#pragma unroll
                for (int k = 0; k < 4; k++) acc[mi][ni][k] = 0.f;

        cp_wait<2>();
        __syncwarp();
#pragma unroll
        for (int q = 0; q < 4; q++) {
            const int base = (w * 8 + q) * 256 + (lane >> 2) * 8 + (lane & 3) * 2;
            float2 bf[4];
#pragma unroll
            for (int ni = 0; ni < 4; ni++)
                bf[ni] = *reinterpret_cast<const float2*>(&sB[base + ni * 64]);
#pragma unroll
            for (int mi = 0; mi < 3; mi++)
#pragma unroll
                for (int ni = 0; ni < 4; ni++)
                    mma_tf32_f(acc[mi][ni], aw[q][mi], bf[ni]);
        }
        cp_wait<1>();
        __syncwarp();
#pragma unroll
        for (int q = 4; q < 8; q++) {
            const int base = (w * 8 + q) * 256 + (lane >> 2) * 8 + (lane & 3) * 2;
            float2 bf[4];
#pragma unroll
            for (int ni = 0; ni < 4; ni++)
                bf[ni] = *reinterpret_cast<const float2*>(&sB[base + ni * 64]);
#pragma unroll
            for (int mi = 0; mi < 3; mi++)
#pragma unroll
                for (int ni = 0; ni < 4; ni++)
                    mma_tf32_f(acc[mi][ni], aw[q][mi], bf[ni]);
        }

#pragma unroll
        for (int mi = 0; mi < 3; mi++)
#pragma unroll
            for (int ni = 0; ni < 4; ni++) {
                sRed2[(((w * 3 + mi) * 4 + ni) * 2 + 0) * 32 + lane] =
                    make_float2(acc[mi][ni][0], acc[mi][ni][1]);
                sRed2[(((w * 3 + mi) * 4 + ni) * 2 + 1) * 32 + lane] =
                    make_float2(acc[mi][ni][2], acc[mi][ni][3]);
            }
        __syncthreads();

        float esum[3][2];
#pragma unroll
        for (int mi = 0; mi < 3; mi++) {
            float2 a0 = sRed2[(((0 * 3 + mi) * 4 + we_ni) * 2 + we_rr) * 32 + lane];
#pragma unroll
            for (int ww = 1; ww < 8; ww++) {
                float2 p = sRed2[(((ww * 3 + mi) * 4 + we_ni) * 2 + we_rr) * 32 + lane];
                a0.x += p.x; a0.y += p.y;
            }
            esum[mi][0] = a0.x; esum[mi][1] = a0.y;
        }
        const int row = we_rr * 8 + (lane >> 2);
        const int kg = c16 + row;
        const float* xpb = sXp + (s & 1) * 1536;
        float hnew2[2];
#pragma unroll
        for (int cc = 0; cc < 2; cc++) {
            int b = we_ni * 8 + 2 * (lane & 3) + cc;
            float rpre = esum[0][cc] + sBias[row];
            float zpre = esum[1][cc] + sBias[16 + row];
            float npre = esum[2][cc] + sBias[32 + row];
            float xr  = xpb[row * 32 + b];
            float xz  = xpb[(16 + row) * 32 + b];
            float xnv = xpb[(32 + row) * 32 + b];
            float rg = 1.0f / (1.0f + __expf(-(xr + rpre)));
            float zg = 1.0f / (1.0f + __expf(-(xz + zpre)));
            float narg = xnv + rg * npre;
            float ng = 2.0f / (1.0f + __expf(-2.0f * narg)) - 1.0f;
            int hoff = (kg >> 3) * 256 + b * 8 + (kg & 3) * 2 + ((kg >> 2) & 1);
            float hold = sB[hoff];
            float hnew = (1.0f - zg) * ng + zg * hold;
            hwr[hoff] = hnew;
            hnew2[cc] = hnew;
        }
        __syncthreads();
        if (tid == 0) {
            __threadfence();
            strlx(f1 + c * 32, (unsigned)(s + 1));
        }

#pragma unroll
        for (int cc = 0; cc < 2; cc++) {
            int b = we_ni * 8 + 2 * (lane & 3) + cc;
            float hnew = hnew2[cc];
            float g = 0.5f * hnew * (1.0f + erff(hnew * 0.70710678118f));
            out[((size_t)b * TT + t) * (size_t)(2 * HH) + (size_t)dir * HH + kg] = g;
        }
    }
}

// ---------------- launcher ----------------
extern "C" void kernel_launch(void* const* d_in, const int* in_sizes, int n_in,
                              void* d_out, int out_size) {
    const float* x       = (const float*)d_in[0];
    const float* ln_g    = (const float*)d_in[1];
    const float* ln_b    = (const float*)d_in[2];
    const float* w_ih_f  = (const float*)d_in[3];
    const float* w_hh_f  = (const float*)d_in[4];
    const float* b_ih_f  = (const float*)d_in[5];
    const float* b_hh_f  = (const float*)d_in[6];
    const float* w_ih_b  = (const float*)d_in[7];
    const float* w_hh_b  = (const float*)d_in[8];
    const float* b_ih_b  = (const float*)d_in[9];
    const float* b_hh_b  = (const float*)d_in[10];
    float* out = (float*)d_out;

    static bool attr_done = false;
    if (!attr_done) {
        cudaFuncSetAttribute(gemm_kernel, cudaFuncAttributeMaxDynamicSharedMemorySize,
                             GEMM_SMEM_BYTES);
        cudaFuncSetAttribute(rec_kernel, cudaFuncAttributeMaxDynamicSharedMemorySize,
                             REC_SMEM_BYTES);
        attr_done = true;
    }

    prep_kernel<<<2048, 256>>>(w_ih_f, w_hh_f, w_ih_b, w_hh_b);
    ln_kernel<<<BATCH * TT, 128>>>(x, ln_g, ln_b);
    gemm_kernel<<<dim3(256, 12, 2), 256, GEMM_SMEM_BYTES>>>(b_ih_f, b_ih_b);
    rec_kernel<<<dim3(NCTA_PER_DIR, 2), 256, REC_SMEM_BYTES>>>(b_hh_f, b_hh_b, out);
}

// round 14
// speedup vs baseline: 1.5088x; 1.1456x over previous
#include <cuda_runtime.h>
#include <cuda_bf16.h>
#include <cuda_fp16.h>
#include <cstdint>
#include <cstddef>

#define BATCH 32
#define TT    1024
#define II    512
#define HH    512
#define G3    1536
#define NCTA_PER_DIR 32

// ---------------- device scratch ----------------
__device__ __half  d_xnh[(size_t)BATCH * TT * II];      // LN output (fp16), [b][t][i]
__device__ float   d_xp[(size_t)2 * TT * G3 * BATCH];
__device__ __half2 d_wAh[786432];                        // fragment-packed fp16 W_ih (gemm)
__device__ __half2 d_wHh[786432];                        // fragment-packed fp16 W_hh (rec)
__device__ __half  d_hh[2 * 4 * 16384];                  // h ring (fp16 b-fragment order)
__device__ unsigned int d_f1[2 * 32 * 32];               // produce flags, 128B padded

// ---------------- helpers ----------------
__device__ __forceinline__ uint32_t smem_u32(const void* p) {
    return (uint32_t)__cvta_generic_to_shared(p);
}
__device__ __forceinline__ void cp16(void* smem_dst, const void* gmem_src) {
    asm volatile("cp.async.cg.shared.global [%0], [%1], 16;"
                 :: "r"(smem_u32(smem_dst)), "l"(gmem_src));
}
__device__ __forceinline__ void cp_commit() { asm volatile("cp.async.commit_group;"); }
template <int N> __device__ __forceinline__ void cp_wait() {
    asm volatile("cp.async.wait_group %0;" :: "n"(N));
}
__device__ __forceinline__ unsigned ldacq(const unsigned* p) {
    unsigned v; asm volatile("ld.acquire.gpu.global.u32 %0, [%1];" : "=r"(v) : "l"(p)); return v;
}
__device__ __forceinline__ void strlx(unsigned* p, unsigned v) {
    asm volatile("st.relaxed.gpu.global.u32 [%0], %1;" :: "l"(p), "r"(v));
}
__device__ __forceinline__ void mma_f16(float* d, const float4& a, uint32_t b0, uint32_t b1) {
    asm volatile(
        "mma.sync.aligned.m16n8k16.row.col.f32.f16.f16.f32 "
        "{%0,%1,%2,%3},{%4,%5,%6,%7},{%8,%9},{%0,%1,%2,%3};"
        : "+f"(d[0]), "+f"(d[1]), "+f"(d[2]), "+f"(d[3])
        : "r"(__float_as_uint(a.x)), "r"(__float_as_uint(a.y)),
          "r"(__float_as_uint(a.z)), "r"(__float_as_uint(a.w)),
          "r"(b0), "r"(b1));
}
__device__ __forceinline__ void mma_f16u(float* d, const uint4& a, uint32_t b0, uint32_t b1) {
    asm volatile(
        "mma.sync.aligned.m16n8k16.row.col.f32.f16.f16.f32 "
        "{%0,%1,%2,%3},{%4,%5,%6,%7},{%8,%9},{%0,%1,%2,%3};"
        : "+f"(d[0]), "+f"(d[1]), "+f"(d[2]), "+f"(d[3])
        : "r"(a.x), "r"(a.y), "r"(a.z), "r"(a.w), "r"(b0), "r"(b1));
}
__device__ __forceinline__ int gate_row(int c, int j) {
    return (j < 16) ? (c * 16 + j)
         : (j < 32) ? (512 + c * 16 + (j - 16))
                    : (1024 + c * 16 + (j - 32));
}

// ---------------- kernel 0: prep ----------------
__global__ void prep_kernel(const float* __restrict__ wihf, const float* __restrict__ whhf,
                            const float* __restrict__ wihb, const float* __restrict__ whhb) {
    int idx = blockIdx.x * blockDim.x + threadIdx.x;
    int stride = gridDim.x * blockDim.x;
    // fp16 W_ih a-fragments (gemm): [dir][by][kb][(wm*4+mi)*2+kstep][lane][reg]
    for (int i = idx; i < 786432; i += stride) {
        int tmp = i;
        int reg   = tmp & 3;  tmp >>= 2;
        int lane  = tmp & 31; tmp >>= 5;
        int idx16 = tmp & 15; tmp >>= 4;
        int kb    = tmp & 15; tmp >>= 4;
        int by    = tmp % 12;
        int dir   = tmp / 12;
        int kstep = idx16 & 1, mi = (idx16 >> 1) & 3, wm = idx16 >> 3;
        int g = by * 128 + wm * 64 + mi * 16 + (lane >> 2) + (reg & 1) * 8;
        int k = kb * 32 + kstep * 16 + (lane & 3) * 2 + (reg >> 1) * 8;
        const float* w = dir ? wihb : wihf;
        d_wAh[i] = __floats2half2_rn(w[g * II + k], w[g * II + k + 1]);
    }
    // fp16 W_hh a-fragments (rec): [dir][c][kk16][mi][lane][comp]
    for (int i = idx; i < 786432; i += stride) {
        int comp = i & 3;
        int lane = (i >> 2) & 31;
        int mi   = (i >> 7) % 3;
        int kk16 = ((i >> 7) / 3) & 31;
        int c    = (i / 12288) % 32;
        int dir  = i / 393216;
        int j = mi * 16 + (lane >> 2) + (comp & 1) * 8;
        int k = kk16 * 16 + (lane & 3) * 2 + (comp >> 1) * 8;
        const float* w = dir ? whhb : whhf;
        int g = gate_row(c, j);
        d_wHh[i] = __floats2half2_rn(w[g * II + k], w[g * II + k + 1]);
    }
    for (int i = idx; i < 2 * 4 * 16384 / 2; i += stride)
        reinterpret_cast<uint32_t*>(d_hh)[i] = 0u;
    for (int i = idx; i < 2 * 32 * 32; i += stride) d_f1[i] = 0u;
}

// ---------------- kernel 1: LayerNorm (fp16 output) ----------------
__global__ void ln_kernel(const float* __restrict__ x, const float* __restrict__ gamma,
                          const float* __restrict__ beta) {
    int row = blockIdx.x;
    const float* xr = x + (size_t)row * II;
    int tid = threadIdx.x;
    float v[4]; float s = 0.f, q = 0.f;
#pragma unroll
    for (int k = 0; k < 4; k++) {
        v[k] = xr[tid + 128 * k];
        s += v[k]; q += v[k] * v[k];
    }
#pragma unroll
    for (int o = 16; o > 0; o >>= 1) {
        s += __shfl_xor_sync(0xffffffffu, s, o);
        q += __shfl_xor_sync(0xffffffffu, q, o);
    }
    __shared__ float ws[4], wq[4];
    if ((tid & 31) == 0) { ws[tid >> 5] = s; wq[tid >> 5] = q; }
    __syncthreads();
    s = ws[0] + ws[1] + ws[2] + ws[3];
    q = wq[0] + wq[1] + wq[2] + wq[3];
    float mu = s * (1.0f / 512.0f);
    float var = q * (1.0f / 512.0f) - mu * mu;
    float rstd = rsqrtf(var + 1e-5f);
#pragma unroll
    for (int k = 0; k < 4; k++) {
        int i = tid + 128 * k;
        d_xnh[(size_t)row * II + i] = __float2half_rn((v[k] - mu) * rstd * gamma[i] + beta[i]);
    }
}

// ---------------- kernel 2: input-projection GEMM (fp16 m16n8k16) ----------------
#define GEMM_SMEM_BYTES 73728
__global__ void __launch_bounds__(256)
gemm_kernel(const float* __restrict__ bihf, const float* __restrict__ bihb) {
    extern __shared__ char smem[];
    int bx = blockIdx.x, by = blockIdx.y, dir = blockIdx.z;
    int tid = threadIdx.x, lane = tid & 31, wid = tid >> 5;
    int wm = wid & 1, wn = wid >> 1;
    const float* bih = dir ? bihb : bihf;
    const char* Abase = reinterpret_cast<const char*>(d_wAh) +
                        ((size_t)((dir * 12 + by) * 16)) * 8192;

    auto load_tiles = [&](int kb, int buf) {
        char* Ab = smem + buf * 8192;
        const char* asrc = Abase + (size_t)kb * 8192;
#pragma unroll
        for (int u = 0; u < 2; u++) {
            int o = tid + 256 * u;
            cp16(Ab + o * 16, asrc + o * 16);
        }
        char* Bb = smem + 16384 + buf * 10240;
#pragma unroll
        for (int u = 0; u < 2; u++) {
            int o = tid + 256 * u;
            int col = o >> 2, seg = o & 3;
            int n = bx * 128 + col;
            int t = n >> 5, b = n & 31;
            cp16(Bb + col * 80 + seg * 16,
                 d_xnh + ((size_t)b * TT + t) * II + kb * 32 + seg * 8);
        }
    };

    float acc[4][4][4];
#pragma unroll
    for (int i = 0; i < 4; i++)
#pragma unroll
        for (int j = 0; j < 4; j++)
#pragma unroll
            for (int k = 0; k < 4; k++) acc[i][j][k] = 0.f;

    load_tiles(0, 0); cp_commit();
    for (int kb = 0; kb < 16; kb++) {
        if (kb + 1 < 16) { load_tiles(kb + 1, (kb + 1) & 1); cp_commit(); cp_wait<1>(); }
        else cp_wait<0>();
        __syncthreads();
        const float4* As4 = reinterpret_cast<const float4*>(smem + (kb & 1) * 8192);
        const __half* Bs_ = reinterpret_cast<const __half*>(smem + 16384 + (kb & 1) * 10240);
#pragma unroll
        for (int kstep = 0; kstep < 2; kstep++) {
            float4 af[4];
            uint32_t bf[4][2];
#pragma unroll
            for (int mi = 0; mi < 4; mi++)
                af[mi] = As4[((wm * 4 + mi) * 2 + kstep) * 32 + lane];
#pragma unroll
            for (int ni = 0; ni < 4; ni++) {
                int c0 = wn * 32 + ni * 8 + (lane >> 2);
                const __half* bp = Bs_ + c0 * 40 + kstep * 16 + (lane & 3) * 2;
                bf[ni][0] = *reinterpret_cast<const uint32_t*>(bp);
                bf[ni][1] = *reinterpret_cast<const uint32_t*>(bp + 8);
            }
#pragma unroll
            for (int mi = 0; mi < 4; mi++)
#pragma unroll
                for (int ni = 0; ni < 4; ni++)
                    mma_f16(acc[mi][ni], af[mi], bf[ni][0], bf[ni][1]);
        }
        __syncthreads();
    }

    float* sC = reinterpret_cast<float*>(smem);
#pragma unroll
    for (int mi = 0; mi < 4; mi++)
#pragma unroll
        for (int ni = 0; ni < 4; ni++)
#pragma unroll
            for (int rr = 0; rr < 2; rr++) {
                int gl = wm * 64 + mi * 16 + (lane >> 2) + rr * 8;
                int nl = wn * 32 + ni * 8 + 2 * (lane & 3);
                *reinterpret_cast<float2*>(&sC[gl * 132 + nl]) =
                    make_float2(acc[mi][ni][rr * 2 + 0], acc[mi][ni][rr * 2 + 1]);
            }
    __syncthreads();

    const int t0 = bx * 4;
    const size_t dbase = (size_t)dir * TT * (size_t)(G3 * BATCH);
#pragma unroll
    for (int k2 = 0; k2 < 16; k2++) {
        int idx = tid + 256 * k2;
        int g  = idx >> 5;
        int n4 = idx & 31;
        int tl = n4 >> 3;
        int b  = (n4 & 7) * 4;
        float4 v = *reinterpret_cast<const float4*>(&sC[g * 132 + n4 * 4]);
        float bias = bih[by * 128 + g];
        v.x += bias; v.y += bias; v.z += bias; v.w += bias;
        size_t off = dbase + (size_t)(t0 + tl) * (G3 * BATCH) + (size_t)(by * 128 + g) * BATCH + b;
        *reinterpret_cast<float4*>(d_xp + off) = v;
    }
}

// ---------------- kernel 3: persistent recurrence (fp16 MMA + register h carry) ----------------
// smem floats: sRed2 12288 (48KB) | sBh 8192 (32KB as half) | sXp 3072 | sBias 48
#define REC_SMEM_FLOATS (12288 + 8192 + 3072 + 48)
#define REC_SMEM_BYTES  (REC_SMEM_FLOATS * 4)

__global__ void __launch_bounds__(256, 1)
rec_kernel(const float* __restrict__ bhhf, const float* __restrict__ bhhb,
           float* __restrict__ out) {
    extern __shared__ float smf[];
    float2* sRed2 = reinterpret_cast<float2*>(smf);
    __half* sBh   = reinterpret_cast<__half*>(smf + 12288);   // 16384 halves (32 k16-chunks)
    float*  sXp   = smf + 12288 + 8192;
    float*  sBias = sXp + 3072;

    const int c = blockIdx.x, dir = blockIdx.y;
    const int tid = threadIdx.x, lane = tid & 31, w = tid >> 5;
    const int c16 = c * 16;

    // register-resident fp16 W fragments: warp w owns kk16 = 4w .. 4w+3
    uint4 aw[4][3];
    {
        const uint4* wsrc = reinterpret_cast<const uint4*>(d_wHh) +
                            ((size_t)(dir * 32 + c)) * 32 * 3 * 32;
#pragma unroll
        for (int q = 0; q < 4; q++)
#pragma unroll
            for (int mi = 0; mi < 3; mi++)
                aw[q][mi] = wsrc[(((w * 4 + q) * 3) + mi) * 32 + lane];
    }
    if (tid < 48) sBias[tid] = (dir ? bhhb : bhhf)[gate_row(c, tid)];
    __syncthreads();

    __half* hbase = d_hh + (size_t)dir * 4 * 16384;
    unsigned* f1 = d_f1 + dir * 1024;

    {
        const int t0 = dir ? (TT - 1) : 0;
        const float* xps = d_xp + ((size_t)dir * TT + t0) * (size_t)(G3 * BATCH);
        for (int o = tid; o < 384; o += 256) {
            int j = o >> 3, seg = o & 7;
            cp16(&sXp[(j * 32 + seg * 4)], xps + (size_t)gate_row(c, j) * BATCH + seg * 4);
        }
        cp_commit();
    }

    const int we_ni = w & 3, we_rr = w >> 2;
    float hprev[2] = {0.f, 0.f};   // register h carry: h(s)[kg][b] for this thread's fixed (kg,b)

    for (int s = 0; s < TT; s++) {
        const int t = dir ? (TT - 1 - s) : s;
        const __half* hrd = hbase + (size_t)(s & 3) * 16384;
        __half* hwr = hbase + (size_t)((s + 1) & 3) * 16384;

        if (s > 0) {
            const unsigned* fp = f1 + (4 * w + (lane & 3)) * 32;
            unsigned v;
            do { v = ldacq(fp); } while (__any_sync(0xffffffffu, v < (unsigned)s));
        }
        // my 4KB fp16 h chunk as two 2KB groups (A: chunks 0-1, B: chunks 2-3)
        {
            const __half* src = hrd + w * 2048;
            __half* dst = sBh + w * 2048;
#pragma unroll
            for (int r = 0; r < 4; r++)
                cp16(dst + (lane + r * 32) * 8, src + (lane + r * 32) * 8);
            cp_commit();
#pragma unroll
            for (int r = 4; r < 8; r++)
                cp16(dst + (lane + r * 32) * 8, src + (lane + r * 32) * 8);
            cp_commit();
        }
        {
            int tn = dir ? (TT - 2 - s) : (s + 1);
            if (tn < 0) tn = 0; if (tn >= TT) tn = TT - 1;
            const float* xps = d_xp + ((size_t)dir * TT + tn) * (size_t)(G3 * BATCH);
            float* dst = sXp + ((s + 1) & 1) * 1536;
            for (int o = tid; o < 384; o += 256) {
                int j = o >> 3, seg = o & 7;
                cp16(dst + j * 32 + seg * 4, xps + (size_t)gate_row(c, j) * BATCH + seg * 4);
            }
            cp_commit();
        }
        // pending: xp(s), A, B, xp(s+1)

        float acc[3][4][4];
#pragma unroll
        for (int mi = 0; mi < 3; mi++)
#pragma unroll
            for (int ni = 0; ni < 4; ni++)
#pragma unroll
                for (int k = 0; k < 4; k++) acc[mi][ni][k] = 0.f;

        cp_wait<2>();
        __syncwarp();
#pragma unroll
        for (int q = 0; q < 2; q++) {
            const __half* cb = sBh + (w * 4 + q) * 512;
#pragma unroll
            for (int ni = 0; ni < 4; ni++) {
                uint2 bf = *reinterpret_cast<const uint2*>(cb + ni * 128 + lane * 4);
#pragma unroll
                for (int mi = 0; mi < 3; mi++)
                    mma_f16u(acc[mi][ni], aw[q][mi], bf.x, bf.y);
            }
        }
        cp_wait<1>();
        __syncwarp();
#pragma unroll
        for (int q = 2; q < 4; q++) {
            const __half* cb = sBh + (w * 4 + q) * 512;
#pragma unroll
            for (int ni = 0; ni < 4; ni++) {
                uint2 bf = *reinterpret_cast<const uint2*>(cb + ni * 128 + lane * 4);
#pragma unroll
                for (int mi = 0; mi < 3; mi++)
                    mma_f16u(acc[mi][ni], aw[q][mi], bf.x, bf.y);
            }
        }

#pragma unroll
        for (int mi = 0; mi < 3; mi++)
#pragma unroll
            for (int ni = 0; ni < 4; ni++) {
                sRed2[(((w * 3 + mi) * 4 + ni) * 2 + 0) * 32 + lane] =
                    make_float2(acc[mi][ni][0], acc[mi][ni][1]);
                sRed2[(((w * 3 + mi) * 4 + ni) * 2 + 1) * 32 + lane] =
                    make_float2(acc[mi][ni][2], acc[mi][ni][3]);
            }
        __syncthreads();   // sync1

        float esum[3][2];
#pragma unroll
        for (int mi = 0; mi < 3; mi++) {
            float2 a0 = sRed2[(((0 * 3 + mi) * 4 + we_ni) * 2 + we_rr) * 32 + lane];
#pragma unroll
            for (int ww = 1; ww < 8; ww++) {
                float2 p = sRed2[(((ww * 3 + mi) * 4 + we_ni) * 2 + we_rr) * 32 + lane];
                a0.x += p.x; a0.y += p.y;
            }
            esum[mi][0] = a0.x; esum[mi][1] = a0.y;
        }
        const int row = we_rr * 8 + (lane >> 2);
        const int kg = c16 + row;
        const float* xpb = sXp + (s & 1) * 1536;
        float hnew2[2];
#pragma unroll
        for (int cc = 0; cc < 2; cc++) {
            int b = we_ni * 8 + 2 * (lane & 3) + cc;
            float rpre = esum[0][cc] + sBias[row];
            float zpre = esum[1][cc] + sBias[16 + row];
            float npre = esum[2][cc] + sBias[32 + row];
            float xr  = xpb[row * 32 + b];
            float xz  = xpb[(16 + row) * 32 + b];
            float xnv = xpb[(32 + row) * 32 + b];
            float rg = 1.0f / (1.0f + __expf(-(xr + rpre)));
            float zg = 1.0f / (1.0f + __expf(-(xz + zpre)));
            float narg = xnv + rg * npre;
            float ng = 2.0f / (1.0f + __expf(-2.0f * narg)) - 1.0f;   // tanh
            float hnew = (1.0f - zg) * ng + zg * hprev[cc];
            hprev[cc] = hnew;
            hnew2[cc] = hnew;
            // store fp16 b-fragment element: chunk c, (row, b)
            int off = c * 512 + (b >> 3) * 128 + ((b & 7) * 4 + ((row & 7) >> 1)) * 4
                    + ((row >= 8) ? 2 : 0) + (row & 1);
            hwr[off] = __float2half_rn(hnew);
        }
        __syncthreads();   // sync2
        if (tid == 0) {
            __threadfence();
            strlx(f1 + c * 32, (unsigned)(s + 1));
        }

#pragma unroll
        for (int cc = 0; cc < 2; cc++) {
            int b = we_ni * 8 + 2 * (lane & 3) + cc;
            float hnew = hnew2[cc];
            float g = 0.5f * hnew * (1.0f + erff(hnew * 0.70710678118f));
            out[((size_t)b * TT + t) * (size_t)(2 * HH) + (size_t)dir * HH + kg] = g;
        }
    }
}

// ---------------- launcher ----------------
extern "C" void kernel_launch(void* const* d_in, const int* in_sizes, int n_in,
                              void* d_out, int out_size) {
    const float* x       = (const float*)d_in[0];
    const float* ln_g    = (const float*)d_in[1];
    const float* ln_b    = (const float*)d_in[2];
    const float* w_ih_f  = (const float*)d_in[3];
    const float* w_hh_f  = (const float*)d_in[4];
    const float* b_ih_f  = (const float*)d_in[5];
    const float* b_hh_f  = (const float*)d_in[6];
    const float* w_ih_b  = (const float*)d_in[7];
    const float* w_hh_b  = (const float*)d_in[8];
    const float* b_ih_b  = (const float*)d_in[9];
    const float* b_hh_b  = (const float*)d_in[10];
    float* out = (float*)d_out;

    static bool attr_done = false;
    if (!attr_done) {
        cudaFuncSetAttribute(gemm_kernel, cudaFuncAttributeMaxDynamicSharedMemorySize,
                             GEMM_SMEM_BYTES);
        cudaFuncSetAttribute(rec_kernel, cudaFuncAttributeMaxDynamicSharedMemorySize,
                             REC_SMEM_BYTES);
        attr_done = true;
    }

    prep_kernel<<<2048, 256>>>(w_ih_f, w_hh_f, w_ih_b, w_hh_b);
    ln_kernel<<<BATCH * TT, 128>>>(x, ln_g, ln_b);
    gemm_kernel<<<dim3(256, 12, 2), 256, GEMM_SMEM_BYTES>>>(b_ih_f, b_ih_b);
    rec_kernel<<<dim3(NCTA_PER_DIR, 2), 256, REC_SMEM_BYTES>>>(b_hh_f, b_hh_b, out);
}

// round 15
// speedup vs baseline: 1.5161x; 1.0049x over previous
#include <cuda_runtime.h>
#include <cuda_bf16.h>
#include <cuda_fp16.h>
#include <cstdint>
#include <cstddef>

#define BATCH 32
#define TT    1024
#define II    512
#define HH    512
#define G3    1536
#define NCTA_PER_DIR 32

// ---------------- device scratch ----------------
__device__ __half  d_xnh[(size_t)BATCH * TT * II];      // LN output (fp16), [b][t][i]
__device__ float   d_xp[(size_t)2 * TT * G3 * BATCH];
__device__ __half2 d_wAh[786432];                        // fragment-packed fp16 W_ih (gemm)
__device__ __half2 d_wHh[786432];                        // fragment-packed fp16 W_hh (rec)
__device__ __half  d_hh[2 * 4 * 16384];                  // h ring (fp16 b-fragment order)
__device__ unsigned int d_f1[2 * 32 * 32];               // produce flags, 128B padded

// ---------------- helpers ----------------
__device__ __forceinline__ uint32_t smem_u32(const void* p) {
    return (uint32_t)__cvta_generic_to_shared(p);
}
__device__ __forceinline__ void cp16(void* smem_dst, const void* gmem_src) {
    asm volatile("cp.async.cg.shared.global [%0], [%1], 16;"
                 :: "r"(smem_u32(smem_dst)), "l"(gmem_src));
}
__device__ __forceinline__ void cp_commit() { asm volatile("cp.async.commit_group;"); }
template <int N> __device__ __forceinline__ void cp_wait() {
    asm volatile("cp.async.wait_group %0;" :: "n"(N));
}
__device__ __forceinline__ unsigned ldacq(const unsigned* p) {
    unsigned v; asm volatile("ld.acquire.gpu.global.u32 %0, [%1];" : "=r"(v) : "l"(p)); return v;
}
__device__ __forceinline__ void strel(unsigned* p, unsigned v) {
    asm volatile("st.release.gpu.global.u32 [%0], %1;" :: "l"(p), "r"(v) : "memory");
}
__device__ __forceinline__ void mma_f16(float* d, const float4& a, uint32_t b0, uint32_t b1) {
    asm volatile(
        "mma.sync.aligned.m16n8k16.row.col.f32.f16.f16.f32 "
        "{%0,%1,%2,%3},{%4,%5,%6,%7},{%8,%9},{%0,%1,%2,%3};"
        : "+f"(d[0]), "+f"(d[1]), "+f"(d[2]), "+f"(d[3])
        : "r"(__float_as_uint(a.x)), "r"(__float_as_uint(a.y)),
          "r"(__float_as_uint(a.z)), "r"(__float_as_uint(a.w)),
          "r"(b0), "r"(b1));
}
__device__ __forceinline__ void mma_f16u(float* d, const uint4& a, uint32_t b0, uint32_t b1) {
    asm volatile(
        "mma.sync.aligned.m16n8k16.row.col.f32.f16.f16.f32 "
        "{%0,%1,%2,%3},{%4,%5,%6,%7},{%8,%9},{%0,%1,%2,%3};"
        : "+f"(d[0]), "+f"(d[1]), "+f"(d[2]), "+f"(d[3])
        : "r"(a.x), "r"(a.y), "r"(a.z), "r"(a.w), "r"(b0), "r"(b1));
}
__device__ __forceinline__ int gate_row(int c, int j) {
    return (j < 16) ? (c * 16 + j)
         : (j < 32) ? (512 + c * 16 + (j - 16))
                    : (1024 + c * 16 + (j - 32));
}

// ---------------- kernel 0: prep ----------------
__global__ void prep_kernel(const float* __restrict__ wihf, const float* __restrict__ whhf,
                            const float* __restrict__ wihb, const float* __restrict__ whhb) {
    int idx = blockIdx.x * blockDim.x + threadIdx.x;
    int stride = gridDim.x * blockDim.x;
    // fp16 W_ih a-fragments (gemm): [dir][by][kb][(wm*4+mi)*2+kstep][lane][reg]
    for (int i = idx; i < 786432; i += stride) {
        int tmp = i;
        int reg   = tmp & 3;  tmp >>= 2;
        int lane  = tmp & 31; tmp >>= 5;
        int idx16 = tmp & 15; tmp >>= 4;
        int kb    = tmp & 15; tmp >>= 4;
        int by    = tmp % 12;
        int dir   = tmp / 12;
        int kstep = idx16 & 1, mi = (idx16 >> 1) & 3, wm = idx16 >> 3;
        int g = by * 128 + wm * 64 + mi * 16 + (lane >> 2) + (reg & 1) * 8;
        int k = kb * 32 + kstep * 16 + (lane & 3) * 2 + (reg >> 1) * 8;
        const float* w = dir ? wihb : wihf;
        d_wAh[i] = __floats2half2_rn(w[g * II + k], w[g * II + k + 1]);
    }
    // fp16 W_hh a-fragments (rec): [dir][c][kk16][mi][lane][comp]
    for (int i = idx; i < 786432; i += stride) {
        int comp = i & 3;
        int lane = (i >> 2) & 31;
        int mi   = (i >> 7) % 3;
        int kk16 = ((i >> 7) / 3) & 31;
        int c    = (i / 12288) % 32;
        int dir  = i / 393216;
        int j = mi * 16 + (lane >> 2) + (comp & 1) * 8;
        int k = kk16 * 16 + (lane & 3) * 2 + (comp >> 1) * 8;
        const float* w = dir ? whhb : whhf;
        int g = gate_row(c, j);
        d_wHh[i] = __floats2half2_rn(w[g * II + k], w[g * II + k + 1]);
    }
    for (int i = idx; i < 2 * 4 * 16384 / 2; i += stride)
        reinterpret_cast<uint32_t*>(d_hh)[i] = 0u;
    for (int i = idx; i < 2 * 32 * 32; i += stride) d_f1[i] = 0u;
}

// ---------------- kernel 1: LayerNorm (fp16 output) ----------------
__global__ void ln_kernel(const float* __restrict__ x, const float* __restrict__ gamma,
                          const float* __restrict__ beta) {
    int row = blockIdx.x;
    const float* xr = x + (size_t)row * II;
    int tid = threadIdx.x;
    float v[4]; float s = 0.f, q = 0.f;
#pragma unroll
    for (int k = 0; k < 4; k++) {
        v[k] = xr[tid + 128 * k];
        s += v[k]; q += v[k] * v[k];
    }
#pragma unroll
    for (int o = 16; o > 0; o >>= 1) {
        s += __shfl_xor_sync(0xffffffffu, s, o);
        q += __shfl_xor_sync(0xffffffffu, q, o);
    }
    __shared__ float ws[4], wq[4];
    if ((tid & 31) == 0) { ws[tid >> 5] = s; wq[tid >> 5] = q; }
    __syncthreads();
    s = ws[0] + ws[1] + ws[2] + ws[3];
    q = wq[0] + wq[1] + wq[2] + wq[3];
    float mu = s * (1.0f / 512.0f);
    float var = q * (1.0f / 512.0f) - mu * mu;
    float rstd = rsqrtf(var + 1e-5f);
#pragma unroll
    for (int k = 0; k < 4; k++) {
        int i = tid + 128 * k;
        d_xnh[(size_t)row * II + i] = __float2half_rn((v[k] - mu) * rstd * gamma[i] + beta[i]);
    }
}

// ---------------- kernel 2: input-projection GEMM (fp16 m16n8k16) ----------------
#define GEMM_SMEM_BYTES 73728
__global__ void __launch_bounds__(256)
gemm_kernel(const float* __restrict__ bihf, const float* __restrict__ bihb) {
    extern __shared__ char smem[];
    int bx = blockIdx.x, by = blockIdx.y, dir = blockIdx.z;
    int tid = threadIdx.x, lane = tid & 31, wid = tid >> 5;
    int wm = wid & 1, wn = wid >> 1;
    const float* bih = dir ? bihb : bihf;
    const char* Abase = reinterpret_cast<const char*>(d_wAh) +
                        ((size_t)((dir * 12 + by) * 16)) * 8192;

    auto load_tiles = [&](int kb, int buf) {
        char* Ab = smem + buf * 8192;
        const char* asrc = Abase + (size_t)kb * 8192;
#pragma unroll
        for (int u = 0; u < 2; u++) {
            int o = tid + 256 * u;
            cp16(Ab + o * 16, asrc + o * 16);
        }
        char* Bb = smem + 16384 + buf * 10240;
#pragma unroll
        for (int u = 0; u < 2; u++) {
            int o = tid + 256 * u;
            int col = o >> 2, seg = o & 3;
            int n = bx * 128 + col;
            int t = n >> 5, b = n & 31;
            cp16(Bb + col * 80 + seg * 16,
                 d_xnh + ((size_t)b * TT + t) * II + kb * 32 + seg * 8);
        }
    };

    float acc[4][4][4];
#pragma unroll
    for (int i = 0; i < 4; i++)
#pragma unroll
        for (int j = 0; j < 4; j++)
#pragma unroll
            for (int k = 0; k < 4; k++) acc[i][j][k] = 0.f;

    load_tiles(0, 0); cp_commit();
    for (int kb = 0; kb < 16; kb++) {
        if (kb + 1 < 16) { load_tiles(kb + 1, (kb + 1) & 1); cp_commit(); cp_wait<1>(); }
        else cp_wait<0>();
        __syncthreads();
        const float4* As4 = reinterpret_cast<const float4*>(smem + (kb & 1) * 8192);
        const __half* Bs_ = reinterpret_cast<const __half*>(smem + 16384 + (kb & 1) * 10240);
#pragma unroll
        for (int kstep = 0; kstep < 2; kstep++) {
            float4 af[4];
            uint32_t bf[4][2];
#pragma unroll
            for (int mi = 0; mi < 4; mi++)
                af[mi] = As4[((wm * 4 + mi) * 2 + kstep) * 32 + lane];
#pragma unroll
            for (int ni = 0; ni < 4; ni++) {
                int c0 = wn * 32 + ni * 8 + (lane >> 2);
                const __half* bp = Bs_ + c0 * 40 + kstep * 16 + (lane & 3) * 2;
                bf[ni][0] = *reinterpret_cast<const uint32_t*>(bp);
                bf[ni][1] = *reinterpret_cast<const uint32_t*>(bp + 8);
            }
#pragma unroll
            for (int mi = 0; mi < 4; mi++)
#pragma unroll
                for (int ni = 0; ni < 4; ni++)
                    mma_f16(acc[mi][ni], af[mi], bf[ni][0], bf[ni][1]);
        }
        __syncthreads();
    }

    float* sC = reinterpret_cast<float*>(smem);
#pragma unroll
    for (int mi = 0; mi < 4; mi++)
#pragma unroll
        for (int ni = 0; ni < 4; ni++)
#pragma unroll
            for (int rr = 0; rr < 2; rr++) {
                int gl = wm * 64 + mi * 16 + (lane >> 2) + rr * 8;
                int nl = wn * 32 + ni * 8 + 2 * (lane & 3);
                *reinterpret_cast<float2*>(&sC[gl * 132 + nl]) =
                    make_float2(acc[mi][ni][rr * 2 + 0], acc[mi][ni][rr * 2 + 1]);
            }
    __syncthreads();

    const int t0 = bx * 4;
    const size_t dbase = (size_t)dir * TT * (size_t)(G3 * BATCH);
#pragma unroll
    for (int k2 = 0; k2 < 16; k2++) {
        int idx = tid + 256 * k2;
        int g  = idx >> 5;
        int n4 = idx & 31;
        int tl = n4 >> 3;
        int b  = (n4 & 7) * 4;
        float4 v = *reinterpret_cast<const float4*>(&sC[g * 132 + n4 * 4]);
        float bias = bih[by * 128 + g];
        v.x += bias; v.y += bias; v.z += bias; v.w += bias;
        size_t off = dbase + (size_t)(t0 + tl) * (G3 * BATCH) + (size_t)(by * 128 + g) * BATCH + b;
        *reinterpret_cast<float4*>(d_xp + off) = v;
    }
}

// ---------------- kernel 3: persistent recurrence (fp16 MMA, reg h carry, split-role publish) ----------------
#define REC_SMEM_FLOATS (12288 + 8192 + 3072 + 48)
#define REC_SMEM_BYTES  (REC_SMEM_FLOATS * 4)

__global__ void __launch_bounds__(256, 1)
rec_kernel(const float* __restrict__ bhhf, const float* __restrict__ bhhb,
           float* __restrict__ out) {
    extern __shared__ float smf[];
    float2* sRed2 = reinterpret_cast<float2*>(smf);
    __half* sBh   = reinterpret_cast<__half*>(smf + 12288);   // 16384 halves (32 k16-chunks)
    float*  sXp   = smf + 12288 + 8192;
    float*  sBias = sXp + 3072;

    const int c = blockIdx.x, dir = blockIdx.y;
    const int tid = threadIdx.x, lane = tid & 31, w = tid >> 5;
    const int c16 = c * 16;

    // register-resident fp16 W fragments: warp w owns kk16 = 4w .. 4w+3
    uint4 aw[4][3];
    {
        const uint4* wsrc = reinterpret_cast<const uint4*>(d_wHh) +
                            ((size_t)(dir * 32 + c)) * 32 * 3 * 32;
#pragma unroll
        for (int q = 0; q < 4; q++)
#pragma unroll
            for (int mi = 0; mi < 3; mi++)
                aw[q][mi] = wsrc[(((w * 4 + q) * 3) + mi) * 32 + lane];
    }
    if (tid < 48) sBias[tid] = (dir ? bhhb : bhhf)[gate_row(c, tid)];
    __syncthreads();

    __half* hbase = d_hh + (size_t)dir * 4 * 16384;
    unsigned* f1 = d_f1 + dir * 1024;

    {
        const int t0 = dir ? (TT - 1) : 0;
        const float* xps = d_xp + ((size_t)dir * TT + t0) * (size_t)(G3 * BATCH);
        for (int o = tid; o < 384; o += 256) {
            int j = o >> 3, seg = o & 7;
            cp16(&sXp[(j * 32 + seg * 4)], xps + (size_t)gate_row(c, j) * BATCH + seg * 4);
        }
        cp_commit();
    }

    const int we_ni = w & 3, we_rr = w >> 2;
    float hprev[2] = {0.f, 0.f};   // register h carry: this thread's fixed (kg,b)

    for (int s = 0; s < TT; s++) {
        const int t = dir ? (TT - 1 - s) : s;
        const __half* hrd = hbase + (size_t)(s & 3) * 16384;
        __half* hwr = hbase + (size_t)((s + 1) & 3) * 16384;

        if (s > 0) {
            const unsigned* fp = f1 + (4 * w + (lane & 3)) * 32;
            unsigned v;
            do { v = ldacq(fp); } while (__any_sync(0xffffffffu, v < (unsigned)s));
        }
        // my 4KB fp16 h chunk as two 2KB groups (A: chunks 0-1, B: chunks 2-3)
        {
            const __half* src = hrd + w * 2048;
            __half* dst = sBh + w * 2048;
#pragma unroll
            for (int r = 0; r < 4; r++)
                cp16(dst + (lane + r * 32) * 8, src + (lane + r * 32) * 8);
            cp_commit();
#pragma unroll
            for (int r = 4; r < 8; r++)
                cp16(dst + (lane + r * 32) * 8, src + (lane + r * 32) * 8);
            cp_commit();
        }
        {
            int tn = dir ? (TT - 2 - s) : (s + 1);
            if (tn < 0) tn = 0; if (tn >= TT) tn = TT - 1;
            const float* xps = d_xp + ((size_t)dir * TT + tn) * (size_t)(G3 * BATCH);
            float* dst = sXp + ((s + 1) & 1) * 1536;
            for (int o = tid; o < 384; o += 256) {
                int j = o >> 3, seg = o & 7;
                cp16(dst + j * 32 + seg * 4, xps + (size_t)gate_row(c, j) * BATCH + seg * 4);
            }
            cp_commit();
        }
        // pending: xp(s), A, B, xp(s+1)

        float acc[3][4][4];
#pragma unroll
        for (int mi = 0; mi < 3; mi++)
#pragma unroll
            for (int ni = 0; ni < 4; ni++)
#pragma unroll
                for (int k = 0; k < 4; k++) acc[mi][ni][k] = 0.f;

        cp_wait<2>();
        __syncwarp();
#pragma unroll
        for (int q = 0; q < 2; q++) {
            const __half* cb = sBh + (w * 4 + q) * 512;
#pragma unroll
            for (int ni = 0; ni < 4; ni++) {
                uint2 bf = *reinterpret_cast<const uint2*>(cb + ni * 128 + lane * 4);
#pragma unroll
                for (int mi = 0; mi < 3; mi++)
                    mma_f16u(acc[mi][ni], aw[q][mi], bf.x, bf.y);
            }
        }
        cp_wait<1>();
        __syncwarp();
#pragma unroll
        for (int q = 2; q < 4; q++) {
            const __half* cb = sBh + (w * 4 + q) * 512;
#pragma unroll
            for (int ni = 0; ni < 4; ni++) {
                uint2 bf = *reinterpret_cast<const uint2*>(cb + ni * 128 + lane * 4);
#pragma unroll
                for (int mi = 0; mi < 3; mi++)
                    mma_f16u(acc[mi][ni], aw[q][mi], bf.x, bf.y);
            }
        }

#pragma unroll
        for (int mi = 0; mi < 3; mi++)
#pragma unroll
            for (int ni = 0; ni < 4; ni++) {
                sRed2[(((w * 3 + mi) * 4 + ni) * 2 + 0) * 32 + lane] =
                    make_float2(acc[mi][ni][0], acc[mi][ni][1]);
                sRed2[(((w * 3 + mi) * 4 + ni) * 2 + 1) * 32 + lane] =
                    make_float2(acc[mi][ni][2], acc[mi][ni][3]);
            }
        __syncthreads();   // sync1: partials visible

        float esum[3][2];
#pragma unroll
        for (int mi = 0; mi < 3; mi++) {
            float2 a0 = sRed2[(((0 * 3 + mi) * 4 + we_ni) * 2 + we_rr) * 32 + lane];
#pragma unroll
            for (int ww = 1; ww < 8; ww++) {
                float2 p = sRed2[(((ww * 3 + mi) * 4 + we_ni) * 2 + we_rr) * 32 + lane];
                a0.x += p.x; a0.y += p.y;
            }
            esum[mi][0] = a0.x; esum[mi][1] = a0.y;
        }
        const int row = we_rr * 8 + (lane >> 2);
        const int kg = c16 + row;
        const float* xpb = sXp + (s & 1) * 1536;
        float hnew2[2];
#pragma unroll
        for (int cc = 0; cc < 2; cc++) {
            int b = we_ni * 8 + 2 * (lane & 3) + cc;
            float rpre = esum[0][cc] + sBias[row];
            float zpre = esum[1][cc] + sBias[16 + row];
            float npre = esum[2][cc] + sBias[32 + row];
            float xr  = xpb[row * 32 + b];
            float xz  = xpb[(16 + row) * 32 + b];
            float xnv = xpb[(32 + row) * 32 + b];
            float rg = 1.0f / (1.0f + __expf(-(xr + rpre)));
            float zg = 1.0f / (1.0f + __expf(-(xz + zpre)));
            float narg = xnv + rg * npre;
            float ng = 2.0f / (1.0f + __expf(-2.0f * narg)) - 1.0f;   // tanh
            float hnew = (1.0f - zg) * ng + zg * hprev[cc];
            hprev[cc] = hnew;
            hnew2[cc] = hnew;
            int off = c * 512 + (b >> 3) * 128 + ((b & 7) * 4 + ((row & 7) >> 1)) * 4
                    + ((row >= 8) ? 2 : 0) + (row & 1);
            hwr[off] = __float2half_rn(hnew);
        }

        // split-role publish barrier: warps 1-7 arrive (non-blocking) and race ahead;
        // warp 0 waits for all h(s+1) stores, then release-publishes the flag.
        if (w == 0) {
            asm volatile("bar.sync 1, 256;" ::: "memory");
            if (lane == 0) strel(f1 + c * 32, (unsigned)(s + 1));
        } else {
            asm volatile("bar.arrive 1, 256;" ::: "memory");
        }

        // GELU + output (off the critical path)
#pragma unroll
        for (int cc = 0; cc < 2; cc++) {
            int b = we_ni * 8 + 2 * (lane & 3) + cc;
            float hnew = hnew2[cc];
            float g = 0.5f * hnew * (1.0f + erff(hnew * 0.70710678118f));
            out[((size_t)b * TT + t) * (size_t)(2 * HH) + (size_t)dir * HH + kg] = g;
        }
    }
}

// ---------------- launcher ----------------
extern "C" void kernel_launch(void* const* d_in, const int* in_sizes, int n_in,
                              void* d_out, int out_size) {
    const float* x       = (const float*)d_in[0];
    const float* ln_g    = (const float*)d_in[1];
    const float* ln_b    = (const float*)d_in[2];
    const float* w_ih_f  = (const float*)d_in[3];
    const float* w_hh_f  = (const float*)d_in[4];
    const float* b_ih_f  = (const float*)d_in[5];
    const float* b_hh_f  = (const float*)d_in[6];
    const float* w_ih_b  = (const float*)d_in[7];
    const float* w_hh_b  = (const float*)d_in[8];
    const float* b_ih_b  = (const float*)d_in[9];
    const float* b_hh_b  = (const float*)d_in[10];
    float* out = (float*)d_out;

    static bool attr_done = false;
    if (!attr_done) {
        cudaFuncSetAttribute(gemm_kernel, cudaFuncAttributeMaxDynamicSharedMemorySize,
                             GEMM_SMEM_BYTES);
        cudaFuncSetAttribute(rec_kernel, cudaFuncAttributeMaxDynamicSharedMemorySize,
                             REC_SMEM_BYTES);
        attr_done = true;
    }

    prep_kernel<<<2048, 256>>>(w_ih_f, w_hh_f, w_ih_b, w_hh_b);
    ln_kernel<<<BATCH * TT, 128>>>(x, ln_g, ln_b);
    gemm_kernel<<<dim3(256, 12, 2), 256, GEMM_SMEM_BYTES>>>(b_ih_f, b_ih_b);
    rec_kernel<<<dim3(NCTA_PER_DIR, 2), 256, REC_SMEM_BYTES>>>(b_hh_f, b_hh_b, out);
}